// round 2
// baseline (speedup 1.0000x reference)
#include <cuda_runtime.h>
#include <cstdint>
#include <math.h>

#define S_LEN 512
#define BATCH 256
#define IN    256
#define HID   1024
#define SWID  256
#define SDEP  100
#define KTOT  (IN + SWID + HID)   // 1536
#define NB    128
#define NT    256

// ---------------- scratch (no allocations allowed) ----------------
__device__ __align__(16) float g_stackA[BATCH * SDEP * SWID];   // 26.2 MB
__device__ __align__(16) float g_stackB[BATCH * SDEP * SWID];   // 26.2 MB
__device__ __align__(16) float g_Wf[4 * HID * KTOT];            // 25.2 MB frag-ordered weights
__device__ __align__(16) float g_c[BATCH * HID];
__device__ __align__(16) float g_d[2 * BATCH * SWID];
__device__ float g_ctl[2 * BATCH * 3];
__device__ unsigned g_cnt;
__device__ volatile unsigned g_gen;

// ---------------- helpers ----------------
__device__ __forceinline__ float ftf32(float x) {
    float y;
    asm("cvt.rna.tf32.f32 %0, %1;" : "=f"(y) : "f"(x));
    return y;
}

__device__ __forceinline__ void mma_tf32(float c[4], const uint32_t a[4], const uint32_t b[2]) {
    asm volatile(
        "mma.sync.aligned.m16n8k8.row.col.f32.tf32.tf32.f32 "
        "{%0,%1,%2,%3}, {%4,%5,%6,%7}, {%8,%9}, {%0,%1,%2,%3};\n"
        : "+f"(c[0]), "+f"(c[1]), "+f"(c[2]), "+f"(c[3])
        : "r"(a[0]), "r"(a[1]), "r"(a[2]), "r"(a[3]), "r"(b[0]), "r"(b[1]));
}

// ---------------- software grid barrier (all NB blocks resident) ----------------
__device__ __forceinline__ void bar_arrive(unsigned* myGen) {
    __syncthreads();
    if (threadIdx.x == 0) {
        unsigned my = g_gen;
        __threadfence();
        unsigned a = atomicAdd(&g_cnt, 1u);
        if (a == NB - 1) {
            g_cnt = 0;
            __threadfence();
            g_gen = my + 1;
        }
        *myGen = my;
    }
}
__device__ __forceinline__ void bar_wait(unsigned myGen) {
    if (threadIdx.x == 0) {
        while (g_gen == myGen) { }
        __threadfence();
    }
    __syncthreads();
}
__device__ __forceinline__ void gbar() {
    unsigned m;
    bar_arrive(&m);
    bar_wait(m);
}

// ---------------- stack blend: each block does 1/NB of the stack ----------------
__device__ __forceinline__ void blend_range(
    const float* __restrict__ Sp, float* __restrict__ So,
    const float* __restrict__ dbuf, const float* __restrict__ ctlbuf,
    int is_t0, int bid, int tid)
{
    const float4* sin4  = (const float4*)Sp;
    float4*       sout4 = (float4*)So;
    const float4* d4    = (const float4*)dbuf;
    const int per_blk = (BATCH * SDEP * (SWID / 4)) / NB;   // 12800
    for (int ii = tid; ii < per_blk; ii += NT) {
        const int idx = bid * per_blk + ii;
        const int w4   = idx & 63;
        const int jrow = (idx >> 6) % SDEP;
        const int b    = idx / (SDEP * 64);
        const int base = b * SDEP * 64;
        float4 cur = sin4[base + jrow * 64 + w4];
        float4 o;
        if (is_t0) {
            o = cur;
        } else {
            const float pu = ctlbuf[b * 3 + 0];
            const float po = ctlbuf[b * 3 + 1];
            const float nn = ctlbuf[b * 3 + 2];
            float4 up = (jrow == 0) ? d4[b * 64 + w4] : sin4[base + (jrow - 1) * 64 + w4];
            float4 dn = make_float4(0.f, 0.f, 0.f, 0.f);
            if (jrow < SDEP - 1) dn = sin4[base + (jrow + 1) * 64 + w4];
            o.x = nn * cur.x + pu * up.x + po * dn.x;
            o.y = nn * cur.y + pu * up.y + po * dn.y;
            o.z = nn * cur.z + pu * up.z + po * dn.z;
            o.w = nn * cur.w + pu * up.w + po * dn.w;
        }
        sout4[idx] = o;
    }
}

// ---------------- the persistent kernel ----------------
__global__ __launch_bounds__(NT, 2) void stackrnn_persistent(
    const float* __restrict__ x,      // [S, B, IN]
    const float* __restrict__ h0,     // [1, B, H]
    const float* __restrict__ W_ih,   // [4H, IN+SWID]
    const float* __restrict__ W_hh,   // [4H, H]
    const float* __restrict__ b_ih,
    const float* __restrict__ b_hh,
    const float* __restrict__ A_w,    // [3, H]
    const float* __restrict__ A_b,    // [3]
    const float* __restrict__ D_w,    // [SWID, H]
    const float* __restrict__ D_b,    // [SWID]
    float* __restrict__ outs,         // [S, B, H]
    float* __restrict__ stackn)       // [B, SDEP, SWID]
{
    const int bid = blockIdx.x;
    const int tid = threadIdx.x;
    const int warp = tid >> 5, lane = tid & 31;
    const int wm = warp >> 2, wj = warp & 3;
    const int gid = lane >> 2, tig = lane & 3;

    __shared__ float As[64][36];
    __shared__ float As2[32][36];
    __shared__ float Bs2[32][36];

    // ======== phase -1: pre-swizzle weights into fragment order ========
    // layout: slot = (jt*4 + g)*4 + wj ; per (slot, kc): 32 lanes x 8 words
    // word w = ks*2 + p : value = W[g*HID + jt*32 + wj*8 + gid][kc*32 + ks*8 + tig + 4*p]
    for (int idx = bid * NT + tid; idx < 4 * HID * KTOT; idx += NB * NT) {
        const int slot = idx / (48 * 256);
        const int rem  = idx - slot * (48 * 256);
        const int kc   = rem >> 8;
        const int r2   = rem & 255;
        const int ln   = r2 >> 3, w = r2 & 7;
        const int jt = slot >> 4, g = (slot >> 2) & 3, wjj = slot & 3;
        const int gg = ln >> 2, tt = ln & 3;
        const int ks = w >> 1, p = w & 1;
        const int row = g * HID + jt * 32 + wjj * 8 + gg;
        const int k   = kc * 32 + ks * 8 + tt + 4 * p;
        float v = (k < IN + SWID) ? W_ih[(size_t)row * (IN + SWID) + k]
                                  : W_hh[(size_t)row * HID + (k - IN - SWID)];
        g_Wf[idx] = ftf32(v);
    }
    gbar();

    // GEMM tile assignment: 32 j-tiles x 4 m-tiles
    const int jt  = bid & 31;
    const int mt  = bid >> 5;
    const int bm0 = mt * 64;
    const int arow = tid >> 3;           // 0..31
    const int kl   = (tid & 7) << 2;     // 0,4,...,28

    for (int t = 0; t < S_LEN; t++) {
        const float* x_t    = x + (size_t)t * BATCH * IN;
        const float* h_prev = (t == 0) ? h0 : outs + (size_t)(t - 1) * BATCH * HID;
        float*       h_out  = outs + (size_t)t * BATCH * HID;
        const float* Sp = (t & 1) ? g_stackB : g_stackA;   // R_{t-1}
        float*       So = (t & 1) ? g_stackA : g_stackB;   // R_t
        const float* dprev   = g_d   + ((t + 1) & 1) * (BATCH * SWID);
        const float* ctlprev = g_ctl + ((t + 1) & 1) * (BATCH * 3);
        float*       dcur    = g_d   + (t & 1) * (BATCH * SWID);
        float*       ctlcur  = g_ctl + (t & 1) * (BATCH * 3);

        // ---- phase 1: gates GEMM (64m x 128n tile, K=1536) + LSTM pointwise ----
        float acc[2][4][4];
#pragma unroll
        for (int a = 0; a < 2; a++)
#pragma unroll
            for (int g = 0; g < 4; g++)
#pragma unroll
                for (int c = 0; c < 4; c++) acc[a][g][c] = 0.f;

        // per-thread control coefficients for the on-the-fly stack-top blend
        float pu0 = 0.f, po0 = 0.f, nn0 = 1.f, pu1 = 0.f, po1 = 0.f, nn1 = 1.f;
        if (t != 0) {
            const int b0r = bm0 + arow, b1r = bm0 + arow + 32;
            pu0 = ctlprev[b0r * 3 + 0]; po0 = ctlprev[b0r * 3 + 1]; nn0 = ctlprev[b0r * 3 + 2];
            pu1 = ctlprev[b1r * 3 + 0]; po1 = ctlprev[b1r * 3 + 1]; nn1 = ctlprev[b1r * 3 + 2];
        }

        for (int kc = 0; kc < 48; kc++) {
            const int kk = kc * 32 + kl;
            // A tile: xin = [x_t | stack_top(R_t) | h_prev], 64 x 32
#pragma unroll
            for (int rr = 0; rr < 2; rr++) {
                const int m = arow + rr * 32;
                const int b = bm0 + m;
                float4 v;
                if (kk < IN) {
                    v = *(const float4*)(x_t + (size_t)b * IN + kk);
                } else if (kk < IN + SWID) {
                    const int w = kk - IN;
                    float4 s0 = *(const float4*)(Sp + (size_t)b * (SDEP * SWID) + w);
                    if (t == 0) {
                        v = s0;
                    } else {
                        float4 s1 = *(const float4*)(Sp + (size_t)b * (SDEP * SWID) + SWID + w);
                        float4 dv = *(const float4*)(dprev + (size_t)b * SWID + w);
                        const float pu = rr ? pu1 : pu0;
                        const float po = rr ? po1 : po0;
                        const float nn = rr ? nn1 : nn0;
                        v.x = nn * s0.x + pu * dv.x + po * s1.x;
                        v.y = nn * s0.y + pu * dv.y + po * s1.y;
                        v.z = nn * s0.z + pu * dv.z + po * s1.z;
                        v.w = nn * s0.w + pu * dv.w + po * s1.w;
                    }
                } else {
                    v = *(const float4*)(h_prev + (size_t)b * HID + (kk - IN - SWID));
                }
                As[m][kl + 0] = ftf32(v.x); As[m][kl + 1] = ftf32(v.y);
                As[m][kl + 2] = ftf32(v.z); As[m][kl + 3] = ftf32(v.w);
            }
            // B fragments: direct LDG.128 from pre-swizzled weights (L2 resident)
            float4 bA[4], bB[4];
#pragma unroll
            for (int g = 0; g < 4; g++) {
                const int slot = (jt * 4 + g) * 4 + wj;
                const float4* pB = (const float4*)(g_Wf + ((size_t)(slot * 48 + kc) * 32 + lane) * 8);
                bA[g] = pB[0];
                bB[g] = pB[1];
            }
            __syncthreads();
#pragma unroll
            for (int ks = 0; ks < 4; ks++) {
                const int k0 = ks * 8;
                uint32_t a[2][4];
#pragma unroll
                for (int mf = 0; mf < 2; mf++) {
                    const int m0 = wm * 32 + mf * 16;
                    a[mf][0] = __float_as_uint(As[m0 + gid    ][k0 + tig    ]);
                    a[mf][1] = __float_as_uint(As[m0 + 8 + gid][k0 + tig    ]);
                    a[mf][2] = __float_as_uint(As[m0 + gid    ][k0 + tig + 4]);
                    a[mf][3] = __float_as_uint(As[m0 + 8 + gid][k0 + tig + 4]);
                }
#pragma unroll
                for (int g = 0; g < 4; g++) {
                    float2 sel;
                    if (ks == 0)      sel = make_float2(bA[g].x, bA[g].y);
                    else if (ks == 1) sel = make_float2(bA[g].z, bA[g].w);
                    else if (ks == 2) sel = make_float2(bB[g].x, bB[g].y);
                    else              sel = make_float2(bB[g].z, bB[g].w);
                    uint32_t bf[2];
                    bf[0] = __float_as_uint(sel.x);
                    bf[1] = __float_as_uint(sel.y);
#pragma unroll
                    for (int mf = 0; mf < 2; mf++) mma_tf32(acc[mf][g], a[mf], bf);
                }
            }
            __syncthreads();
        }

        // LSTM pointwise epilogue (writes h_t, updates c)
        const int j0 = jt * 32;
#pragma unroll
        for (int mf = 0; mf < 2; mf++) {
#pragma unroll
            for (int cc = 0; cc < 4; cc++) {
                const int row = wm * 32 + mf * 16 + ((cc >> 1) << 3) + gid;
                const int col = wj * 8 + (tig << 1) + (cc & 1);
                const int b = bm0 + row;
                const int j = j0 + col;
                float gi = acc[mf][0][cc] + b_ih[j]           + b_hh[j];
                float gf = acc[mf][1][cc] + b_ih[HID + j]     + b_hh[HID + j];
                float gg = acc[mf][2][cc] + b_ih[2 * HID + j] + b_hh[2 * HID + j];
                float go = acc[mf][3][cc] + b_ih[3 * HID + j] + b_hh[3 * HID + j];
                float iv = 1.f / (1.f + expf(-gi));
                float fv = 1.f / (1.f + expf(-gf));
                float gv = tanhf(gg);
                float ov = 1.f / (1.f + expf(-go));
                const size_t off = (size_t)b * HID + j;
                float cnew = fv * g_c[off] + iv * gv;
                g_c[off]  = cnew;
                h_out[off] = ov * tanhf(cnew);
            }
        }

        // ---- barrier 1 (split): blend overlaps the wait ----
        unsigned myg;
        bar_arrive(&myg);
        // R_t = blend(R_{t-1}, d_{t-1}, ctl_{t-1})  (reads only phase-safe data)
        blend_range(Sp, So, dprev, ctlprev, t == 0, bid, tid);
        bar_wait(myg);

        // ---- phase 2: d = tanh(h @ D_w^T + D_b), controls softmax ----
        if (bid < 64) {
            const int bx = bid & 7, by = bid >> 3;
            const int w0 = bx * 32, bm0d = by * 32;
            float acc2[4] = {0.f, 0.f, 0.f, 0.f};
            for (int kc = 0; kc < HID; kc += 32) {
                const int kk = kc + kl;
                {
                    float4 v = *(const float4*)(h_out + (size_t)(bm0d + arow) * HID + kk);
                    As2[arow][kl + 0] = ftf32(v.x); As2[arow][kl + 1] = ftf32(v.y);
                    As2[arow][kl + 2] = ftf32(v.z); As2[arow][kl + 3] = ftf32(v.w);
                }
                {
                    float4 v = *(const float4*)(D_w + (size_t)(w0 + arow) * HID + kk);
                    Bs2[arow][kl + 0] = ftf32(v.x); Bs2[arow][kl + 1] = ftf32(v.y);
                    Bs2[arow][kl + 2] = ftf32(v.z); Bs2[arow][kl + 3] = ftf32(v.w);
                }
                __syncthreads();
#pragma unroll
                for (int ks = 0; ks < 4; ks++) {
                    const int k0 = ks * 8;
                    uint32_t a[4], bf[2];
                    const int m0 = wm * 16;
                    a[0] = __float_as_uint(As2[m0 + gid    ][k0 + tig    ]);
                    a[1] = __float_as_uint(As2[m0 + 8 + gid][k0 + tig    ]);
                    a[2] = __float_as_uint(As2[m0 + gid    ][k0 + tig + 4]);
                    a[3] = __float_as_uint(As2[m0 + 8 + gid][k0 + tig + 4]);
                    const int n0 = wj * 8;
                    bf[0] = __float_as_uint(Bs2[n0 + gid][k0 + tig    ]);
                    bf[1] = __float_as_uint(Bs2[n0 + gid][k0 + tig + 4]);
                    mma_tf32(acc2, a, bf);
                }
                __syncthreads();
            }
#pragma unroll
            for (int cc = 0; cc < 4; cc++) {
                const int row = wm * 16 + ((cc >> 1) << 3) + gid;
                const int col = wj * 8 + (tig << 1) + (cc & 1);
                const int b = bm0d + row, w = w0 + col;
                dcur[(size_t)b * SWID + w] = tanhf(acc2[cc] + D_b[w]);
            }
        } else if (bid < 72) {
            const int bm0c = (bid - 64) * 32;
            for (int q = 0; q < 4; q++) {
                const int b = bm0c + warp * 4 + q;
                float s0 = 0.f, s1 = 0.f, s2 = 0.f;
                for (int k = lane; k < HID; k += 32) {
                    float hv = h_out[(size_t)b * HID + k];
                    s0 += hv * A_w[k];
                    s1 += hv * A_w[HID + k];
                    s2 += hv * A_w[2 * HID + k];
                }
#pragma unroll
                for (int o = 16; o > 0; o >>= 1) {
                    s0 += __shfl_xor_sync(0xffffffffu, s0, o);
                    s1 += __shfl_xor_sync(0xffffffffu, s1, o);
                    s2 += __shfl_xor_sync(0xffffffffu, s2, o);
                }
                if (lane == 0) {
                    s0 += A_b[0]; s1 += A_b[1]; s2 += A_b[2];
                    float mx = fmaxf(s0, fmaxf(s1, s2));
                    float e0 = expf(s0 - mx), e1 = expf(s1 - mx), e2 = expf(s2 - mx);
                    float inv = 1.f / (e0 + e1 + e2);
                    ctlcur[b * 3 + 0] = e0 * inv;
                    ctlcur[b * 3 + 1] = e1 * inv;
                    ctlcur[b * 3 + 2] = e2 * inv;
                }
            }
        }
        gbar();   // end of step: d_t / ctl_t visible for step t+1
    }

    // ---- final stack: R_512 = blend(R_511, d_511, ctl_511) -> stackn ----
    {
        const float* Sp = g_stackA;                       // R_511 (t=511 wrote A)
        const float* dfin   = g_d   + 1 * (BATCH * SWID); // t=511 wrote slot 1
        const float* ctlfin = g_ctl + 1 * (BATCH * 3);
        blend_range(Sp, stackn, dfin, ctlfin, 0, bid, tid);
    }
}

// ---------------- launch ----------------
extern "C" void kernel_launch(void* const* d_in, const int* in_sizes, int n_in,
                              void* d_out, int out_size)
{
    const float* x    = (const float*)d_in[0];
    const float* h0   = (const float*)d_in[1];
    const float* c0   = (const float*)d_in[2];
    const float* st0  = (const float*)d_in[3];
    const float* W_ih = (const float*)d_in[4];
    const float* W_hh = (const float*)d_in[5];
    const float* b_ih = (const float*)d_in[6];
    const float* b_hh = (const float*)d_in[7];
    const float* A_w  = (const float*)d_in[8];
    const float* A_b  = (const float*)d_in[9];
    const float* D_w  = (const float*)d_in[10];
    const float* D_b  = (const float*)d_in[11];

    float* out    = (float*)d_out;
    float* outs   = out;                                     // [S, B, H]
    float* hn     = outs + (size_t)S_LEN * BATCH * HID;      // [1, B, H]
    float* cn     = hn + (size_t)BATCH * HID;                // [1, B, H]
    float* stackn = cn + (size_t)BATCH * HID;                // [B, SDEP, SWID]

    float *sA, *cbuf;
    cudaGetSymbolAddress((void**)&sA, g_stackA);
    cudaGetSymbolAddress((void**)&cbuf, g_c);

    cudaMemcpyAsync(cbuf, c0, sizeof(float) * BATCH * HID, cudaMemcpyDeviceToDevice);
    cudaMemcpyAsync(sA, st0, sizeof(float) * BATCH * SDEP * SWID, cudaMemcpyDeviceToDevice);

    stackrnn_persistent<<<NB, NT>>>(x, h0, W_ih, W_hh, b_ih, b_hh,
                                    A_w, A_b, D_w, D_b, outs, stackn);

    cudaMemcpyAsync(hn, outs + (size_t)(S_LEN - 1) * BATCH * HID,
                    sizeof(float) * BATCH * HID, cudaMemcpyDeviceToDevice);
    cudaMemcpyAsync(cn, cbuf, sizeof(float) * BATCH * HID, cudaMemcpyDeviceToDevice);
}

// round 3
// speedup vs baseline: 1.2064x; 1.2064x over previous
#include <cuda_runtime.h>
#include <cstdint>
#include <math.h>

#define S_LEN 512
#define BATCH 256
#define IN    256
#define HID   1024
#define SWID  256
#define SDEP  100
#define KTOT  1536
#define IS    (IN + SWID)     // 512
#define NB    128
#define NT    256

// ---------------- scratch (no allocations allowed) ----------------
__device__ __align__(16) float g_stackA[BATCH * SDEP * SWID];   // 26.2 MB
__device__ __align__(16) float g_stackB[BATCH * SDEP * SWID];   // 26.2 MB (also prep scratch)
__device__ __align__(16) float g_Wf[4 * HID * KTOT];            // 25.2 MB frag-ordered weights
__device__ __align__(16) float g_c[BATCH * HID];
__device__ __align__(16) float g_d[2 * BATCH * SWID];
__device__ float g_ctl[2 * BATCH * 3];
__device__ unsigned g_cnt;
__device__ volatile unsigned g_gen;

// ---------------- helpers ----------------
__device__ __forceinline__ float ftf32(float x) {
    float y;
    asm("cvt.rna.tf32.f32 %0, %1;" : "=f"(y) : "f"(x));
    return y;
}

__device__ __forceinline__ void mma_tf32(float c[4], const uint32_t a[4], const uint32_t b[2]) {
    asm volatile(
        "mma.sync.aligned.m16n8k8.row.col.f32.tf32.tf32.f32 "
        "{%0,%1,%2,%3}, {%4,%5,%6,%7}, {%8,%9}, {%0,%1,%2,%3};\n"
        : "+f"(c[0]), "+f"(c[1]), "+f"(c[2]), "+f"(c[3])
        : "r"(a[0]), "r"(a[1]), "r"(a[2]), "r"(a[3]), "r"(b[0]), "r"(b[1]));
}

// ---------------- software grid barrier ----------------
__device__ __forceinline__ void bar_arrive(unsigned* myGen) {
    __syncthreads();
    if (threadIdx.x == 0) {
        unsigned my = g_gen;
        __threadfence();
        unsigned a = atomicAdd(&g_cnt, 1u);
        if (a == NB - 1) {
            g_cnt = 0;
            __threadfence();
            g_gen = my + 1;
        }
        *myGen = my;
    }
}
__device__ __forceinline__ void bar_wait(unsigned myGen) {
    if (threadIdx.x == 0) {
        while (g_gen == myGen) { }
        __threadfence();
    }
    __syncthreads();
}
__device__ __forceinline__ void gbar() {
    unsigned m;
    bar_arrive(&m);
    bar_wait(m);
}

// ---------------- stack blend ----------------
__device__ __forceinline__ void blend_range(
    const float* __restrict__ Sp, float* __restrict__ So,
    const float* __restrict__ dbuf, const float* __restrict__ ctlbuf,
    int is_t0, int bid, int tid)
{
    const float4* sin4  = (const float4*)Sp;
    float4*       sout4 = (float4*)So;
    const float4* d4    = (const float4*)dbuf;
    const int per_blk = (BATCH * SDEP * (SWID / 4)) / NB;   // 12800
    for (int ii = tid; ii < per_blk; ii += NT) {
        const int idx = bid * per_blk + ii;
        const int w4   = idx & 63;
        const int jrow = (idx >> 6) % SDEP;
        const int b    = idx / (SDEP * 64);
        const int base = b * SDEP * 64;
        float4 cur = sin4[base + jrow * 64 + w4];
        float4 o;
        if (is_t0) {
            o = cur;
        } else {
            const float pu = ctlbuf[b * 3 + 0];
            const float po = ctlbuf[b * 3 + 1];
            const float nn = ctlbuf[b * 3 + 2];
            float4 up = (jrow == 0) ? d4[b * 64 + w4] : sin4[base + (jrow - 1) * 64 + w4];
            float4 dn = make_float4(0.f, 0.f, 0.f, 0.f);
            if (jrow < SDEP - 1) dn = sin4[base + (jrow + 1) * 64 + w4];
            o.x = nn * cur.x + pu * up.x + po * dn.x;
            o.y = nn * cur.y + pu * up.y + po * dn.y;
            o.z = nn * cur.z + pu * up.z + po * dn.z;
            o.w = nn * cur.w + pu * up.w + po * dn.w;
        }
        sout4[idx] = o;
    }
}

// ---------------- prep: fused plain weights (tf32), then frag-swizzle ----------------
__global__ void prep_plain(const float* __restrict__ W_ih, const float* __restrict__ W_hh) {
    const int total = 4 * HID * KTOT;
    for (int idx = blockIdx.x * blockDim.x + threadIdx.x; idx < total;
         idx += gridDim.x * blockDim.x) {
        int row = idx / KTOT, k = idx - row * KTOT;
        float v = (k < IS) ? W_ih[(size_t)row * IS + k]
                           : W_hh[(size_t)row * HID + (k - IS)];
        g_stackB[idx] = ftf32(v);
    }
}
// g_Wf layout: idx = ((((jt*8+wj)*2+nf)*48 + kc)*32 + lane)*8 + w ; w = ks*2+p
// value = Wplain[row(n)][k], n = wj*16+nf*8+gid, row(n) = (n>>5)*HID + jt*32 + (n&31),
// k = kc*32 + ks*8 + tig + 4p
__global__ void prep_swz() {
    const int total = 4 * HID * KTOT;
    for (int idx = blockIdx.x * blockDim.x + threadIdx.x; idx < total;
         idx += gridDim.x * blockDim.x) {
        int w    = idx & 7;
        int lane = (idx >> 3) & 31;
        int kc   = (idx >> 8) % 48;
        int t1   = idx / (48 * 256);
        int nf = t1 & 1, wjj = (t1 >> 1) & 7, jt = t1 >> 4;
        int gid = lane >> 2, tig = lane & 3, ks = w >> 1, p = w & 1;
        int n   = wjj * 16 + nf * 8 + gid;
        int row = (n >> 5) * HID + jt * 32 + (n & 31);
        int k   = kc * 32 + ks * 8 + tig + 4 * p;
        g_Wf[idx] = g_stackB[(size_t)row * KTOT + k];
    }
}

// ---------------- the persistent kernel ----------------
__global__ __launch_bounds__(NT, 1) void stackrnn_persistent(
    const float* __restrict__ x,      // [S, B, IN]
    const float* __restrict__ h0,
    const float* __restrict__ b_ih,
    const float* __restrict__ b_hh,
    const float* __restrict__ A_w,
    const float* __restrict__ A_b,
    const float* __restrict__ D_w,
    const float* __restrict__ D_b,
    float* __restrict__ outs,         // [S, B, H]
    float* __restrict__ stackn)       // [B, SDEP, SWID]
{
    // sm is multi-use: GEMM A tiles (2 x 64 x 36 = 4608 floats),
    // epilogue Cs (64 x 132 = 8448), phase-2 As2/Bs2 (2 x 32 x 36)
    __shared__ __align__(16) float sm[8448];

    const int bid = blockIdx.x;
    const int tid = threadIdx.x;
    const int wj = tid >> 5, lane = tid & 31;
    const int gid = lane >> 2, tig = lane & 3;
    const int jt = bid & 31, mt = bid >> 5, bm0 = mt * 64;
    const int arow = tid >> 3;          // 0..31
    const int kl   = (tid & 7) << 2;    // 0,4,...,28
    const int j0 = jt * 32;

    for (int t = 0; t < S_LEN; t++) {
        const float* x_t    = x + (size_t)t * BATCH * IN;
        const float* h_prev = t ? outs + (size_t)(t - 1) * BATCH * HID : h0;
        float*       h_out  = outs + (size_t)t * BATCH * HID;
        const float* Sp = (t & 1) ? g_stackB : g_stackA;
        float*       So = (t & 1) ? g_stackA : g_stackB;
        const float* dprev   = g_d   + ((t + 1) & 1) * (BATCH * SWID);
        const float* ctlprev = g_ctl + ((t + 1) & 1) * (BATCH * 3);
        float*       dcur    = g_d   + (t & 1) * (BATCH * SWID);
        float*       ctlcur  = g_ctl + (t & 1) * (BATCH * 3);

        float pu0 = 0.f, po0 = 0.f, nn0 = 1.f, pu1 = 0.f, po1 = 0.f, nn1 = 1.f;
        if (t) {
            const int b0r = bm0 + arow, b1r = b0r + 32;
            pu0 = ctlprev[b0r * 3 + 0]; po0 = ctlprev[b0r * 3 + 1]; nn0 = ctlprev[b0r * 3 + 2];
            pu1 = ctlprev[b1r * 3 + 0]; po1 = ctlprev[b1r * 3 + 1]; nn1 = ctlprev[b1r * 3 + 2];
        }

        auto ldgA = [&](int kc, float4* v) {
            const int kk = kc * 32 + kl;
#pragma unroll
            for (int rr = 0; rr < 2; rr++) {
                const int b = bm0 + arow + rr * 32;
                float4 q;
                if (kk < IN) {
                    q = *(const float4*)(x_t + (size_t)b * IN + kk);
                } else if (kk < IS) {
                    const int w = kk - IN;
                    float4 s0 = *(const float4*)(Sp + (size_t)b * (SDEP * SWID) + w);
                    if (t == 0) {
                        q = s0;
                    } else {
                        float4 s1 = *(const float4*)(Sp + (size_t)b * (SDEP * SWID) + SWID + w);
                        float4 dv = *(const float4*)(dprev + (size_t)b * SWID + w);
                        const float pu = rr ? pu1 : pu0;
                        const float po = rr ? po1 : po0;
                        const float nn = rr ? nn1 : nn0;
                        q.x = nn * s0.x + pu * dv.x + po * s1.x;
                        q.y = nn * s0.y + pu * dv.y + po * s1.y;
                        q.z = nn * s0.z + pu * dv.z + po * s1.z;
                        q.w = nn * s0.w + pu * dv.w + po * s1.w;
                    }
                } else {
                    q = *(const float4*)(h_prev + (size_t)b * HID + (kk - IS));
                }
                v[rr] = q;
            }
        };
        auto stsA = [&](int buf, const float4* v) {
#pragma unroll
            for (int rr = 0; rr < 2; rr++) {
                const int m = arow + rr * 32;
                float* p = &sm[buf * 2304 + m * 36 + kl];
                p[0] = ftf32(v[rr].x); p[1] = ftf32(v[rr].y);
                p[2] = ftf32(v[rr].z); p[3] = ftf32(v[rr].w);
            }
        };
        auto ldgB = [&](int kc, float4 bb[2][2]) {
#pragma unroll
            for (int nf = 0; nf < 2; nf++) {
                const float4* p = (const float4*)(g_Wf +
                    ((size_t)(((jt * 8 + wj) * 2 + nf) * 48 + kc) * 32 + lane) * 8);
                bb[nf][0] = p[0];
                bb[nf][1] = p[1];
            }
        };

        // ---- phase 1: gates GEMM, warp = 64m x 16n (mf=4, nf=2), no B dup ----
        float acc[4][2][4];
#pragma unroll
        for (int mf = 0; mf < 4; mf++)
#pragma unroll
            for (int nf = 0; nf < 2; nf++)
#pragma unroll
                for (int cc = 0; cc < 4; cc++) acc[mf][nf][cc] = 0.f;

        float4 vA[2], bCur[2][2], bNxt[2][2];
        ldgA(0, vA);
        ldgB(0, bCur);
        stsA(0, vA);
        for (int kc = 0; kc < 48; kc++) {
            const int cur = kc & 1;
            if (kc < 47) { ldgA(kc + 1, vA); ldgB(kc + 1, bNxt); }
            __syncthreads();
#pragma unroll
            for (int ks = 0; ks < 4; ks++) {
                const int k0 = ks * 8;
                uint32_t a[4][4];
#pragma unroll
                for (int mf = 0; mf < 4; mf++) {
                    const float* base = &sm[cur * 2304 + (mf * 16 + gid) * 36 + k0];
                    a[mf][0] = __float_as_uint(base[tig]);
                    a[mf][1] = __float_as_uint(base[8 * 36 + tig]);
                    a[mf][2] = __float_as_uint(base[tig + 4]);
                    a[mf][3] = __float_as_uint(base[8 * 36 + tig + 4]);
                }
#pragma unroll
                for (int nf = 0; nf < 2; nf++) {
                    float2 s;
                    if (ks == 0)      s = make_float2(bCur[nf][0].x, bCur[nf][0].y);
                    else if (ks == 1) s = make_float2(bCur[nf][0].z, bCur[nf][0].w);
                    else if (ks == 2) s = make_float2(bCur[nf][1].x, bCur[nf][1].y);
                    else              s = make_float2(bCur[nf][1].z, bCur[nf][1].w);
                    uint32_t bf[2] = {__float_as_uint(s.x), __float_as_uint(s.y)};
#pragma unroll
                    for (int mf = 0; mf < 4; mf++) mma_tf32(acc[mf][nf], a[mf], bf);
                }
            }
            if (kc < 47) {
                stsA(cur ^ 1, vA);
#pragma unroll
                for (int nf = 0; nf < 2; nf++) {
                    bCur[nf][0] = bNxt[nf][0];
                    bCur[nf][1] = bNxt[nf][1];
                }
            }
        }
        __syncthreads();   // As region dead; reuse as Cs[64][132]

        // scatter acc -> Cs
#pragma unroll
        for (int mf = 0; mf < 4; mf++)
#pragma unroll
            for (int nf = 0; nf < 2; nf++)
#pragma unroll
                for (int cc = 0; cc < 4; cc++) {
                    const int m   = mf * 16 + ((cc >> 1) << 3) + gid;
                    const int col = wj * 16 + nf * 8 + (tig << 1) + (cc & 1);
                    sm[m * 132 + col] = acc[mf][nf][cc];
                }
        __syncthreads();

        // LSTM pointwise: thread -> (row m = tid>>2, 8 cols jb..jb+7)
        {
            const int m  = tid >> 2;
            const int jb = (tid & 3) << 3;
            const int b  = bm0 + m;
            const size_t off = (size_t)b * HID + j0 + jb;
            float GI[8], GF[8], GG[8], GO[8], CC[8], HH[8];
            *(float4*)&GI[0] = *(float4*)&sm[m * 132 + jb];
            *(float4*)&GI[4] = *(float4*)&sm[m * 132 + jb + 4];
            *(float4*)&GF[0] = *(float4*)&sm[m * 132 + 32 + jb];
            *(float4*)&GF[4] = *(float4*)&sm[m * 132 + 32 + jb + 4];
            *(float4*)&GG[0] = *(float4*)&sm[m * 132 + 64 + jb];
            *(float4*)&GG[4] = *(float4*)&sm[m * 132 + 64 + jb + 4];
            *(float4*)&GO[0] = *(float4*)&sm[m * 132 + 96 + jb];
            *(float4*)&GO[4] = *(float4*)&sm[m * 132 + 96 + jb + 4];
            *(float4*)&CC[0] = *(float4*)(g_c + off);
            *(float4*)&CC[4] = *(float4*)(g_c + off + 4);
#pragma unroll
            for (int e = 0; e < 8; e++) {
                const int jg = j0 + jb + e;
                float gi = GI[e] + b_ih[jg]           + b_hh[jg];
                float gf = GF[e] + b_ih[HID + jg]     + b_hh[HID + jg];
                float gg = GG[e] + b_ih[2 * HID + jg] + b_hh[2 * HID + jg];
                float go = GO[e] + b_ih[3 * HID + jg] + b_hh[3 * HID + jg];
                float iv = 1.f / (1.f + expf(-gi));
                float fv = 1.f / (1.f + expf(-gf));
                float gv = tanhf(gg);
                float ov = 1.f / (1.f + expf(-go));
                float cn_ = fv * CC[e] + iv * gv;
                CC[e] = cn_;
                HH[e] = ov * tanhf(cn_);
            }
            *(float4*)(g_c + off)     = *(float4*)&CC[0];
            *(float4*)(g_c + off + 4) = *(float4*)&CC[4];
            *(float4*)(h_out + off)     = *(float4*)&HH[0];
            *(float4*)(h_out + off + 4) = *(float4*)&HH[4];
        }

        // ---- barrier A (split): blend overlaps the wait ----
        unsigned myg;
        bar_arrive(&myg);
        blend_range(Sp, So, dprev, ctlprev, t == 0, bid, tid);
        bar_wait(myg);

        // ---- phase 2: d = tanh(h @ D_w^T + D_b); controls softmax ----
        if (bid < 64) {
            const int bx = bid & 7, by = bid >> 3;
            const int w0 = bx * 32, bm0d = by * 32;
            const int wm2 = (tid >> 5) >> 2, wn2 = (tid >> 5) & 3;
            float acc2[4] = {0.f, 0.f, 0.f, 0.f};
            for (int kc = 0; kc < HID; kc += 32) {
                const int kk = kc + kl;
                {
                    float4 v = *(const float4*)(h_out + (size_t)(bm0d + arow) * HID + kk);
                    float* p = &sm[arow * 36 + kl];
                    p[0] = ftf32(v.x); p[1] = ftf32(v.y); p[2] = ftf32(v.z); p[3] = ftf32(v.w);
                }
                {
                    float4 v = *(const float4*)(D_w + (size_t)(w0 + arow) * HID + kk);
                    float* p = &sm[1152 + arow * 36 + kl];
                    p[0] = ftf32(v.x); p[1] = ftf32(v.y); p[2] = ftf32(v.z); p[3] = ftf32(v.w);
                }
                __syncthreads();
#pragma unroll
                for (int ks = 0; ks < 4; ks++) {
                    const int k0 = ks * 8;
                    uint32_t a[4], bf[2];
                    const int m0 = wm2 * 16;
                    a[0] = __float_as_uint(sm[(m0 + gid) * 36 + k0 + tig]);
                    a[1] = __float_as_uint(sm[(m0 + 8 + gid) * 36 + k0 + tig]);
                    a[2] = __float_as_uint(sm[(m0 + gid) * 36 + k0 + tig + 4]);
                    a[3] = __float_as_uint(sm[(m0 + 8 + gid) * 36 + k0 + tig + 4]);
                    const int n0 = wn2 * 8;
                    bf[0] = __float_as_uint(sm[1152 + (n0 + gid) * 36 + k0 + tig]);
                    bf[1] = __float_as_uint(sm[1152 + (n0 + gid) * 36 + k0 + tig + 4]);
                    mma_tf32(acc2, a, bf);
                }
                __syncthreads();
            }
#pragma unroll
            for (int cc = 0; cc < 4; cc++) {
                const int row = wm2 * 16 + ((cc >> 1) << 3) + gid;
                const int col = wn2 * 8 + (tig << 1) + (cc & 1);
                dcur[(size_t)(bm0d + row) * SWID + w0 + col] = tanhf(acc2[cc] + D_b[w0 + col]);
            }
        } else if (bid < 72) {
            const int warp = tid >> 5;
            const int bm0c = (bid - 64) * 32;
            for (int q = 0; q < 4; q++) {
                const int b = bm0c + warp * 4 + q;
                float s0 = 0.f, s1 = 0.f, s2 = 0.f;
                for (int k = lane; k < HID; k += 32) {
                    float hv = h_out[(size_t)b * HID + k];
                    s0 += hv * A_w[k];
                    s1 += hv * A_w[HID + k];
                    s2 += hv * A_w[2 * HID + k];
                }
#pragma unroll
                for (int o = 16; o > 0; o >>= 1) {
                    s0 += __shfl_xor_sync(0xffffffffu, s0, o);
                    s1 += __shfl_xor_sync(0xffffffffu, s1, o);
                    s2 += __shfl_xor_sync(0xffffffffu, s2, o);
                }
                if (lane == 0) {
                    s0 += A_b[0]; s1 += A_b[1]; s2 += A_b[2];
                    float mx = fmaxf(s0, fmaxf(s1, s2));
                    float e0 = expf(s0 - mx), e1 = expf(s1 - mx), e2 = expf(s2 - mx);
                    float inv = 1.f / (e0 + e1 + e2);
                    ctlcur[b * 3 + 0] = e0 * inv;
                    ctlcur[b * 3 + 1] = e1 * inv;
                    ctlcur[b * 3 + 2] = e2 * inv;
                }
            }
        }
        gbar();   // d_t / ctl_t / stack visible for step t+1
    }

    // ---- final stack: R_512 = blend(R_511, d_511, ctl_511) -> stackn ----
    blend_range(g_stackA, stackn, g_d + BATCH * SWID, g_ctl + BATCH * 3, 0, bid, tid);
}

// ---------------- launch ----------------
extern "C" void kernel_launch(void* const* d_in, const int* in_sizes, int n_in,
                              void* d_out, int out_size)
{
    const float* x    = (const float*)d_in[0];
    const float* h0   = (const float*)d_in[1];
    const float* c0   = (const float*)d_in[2];
    const float* st0  = (const float*)d_in[3];
    const float* W_ih = (const float*)d_in[4];
    const float* W_hh = (const float*)d_in[5];
    const float* b_ih = (const float*)d_in[6];
    const float* b_hh = (const float*)d_in[7];
    const float* A_w  = (const float*)d_in[8];
    const float* A_b  = (const float*)d_in[9];
    const float* D_w  = (const float*)d_in[10];
    const float* D_b  = (const float*)d_in[11];

    float* out    = (float*)d_out;
    float* outs   = out;
    float* hn     = outs + (size_t)S_LEN * BATCH * HID;
    float* cn     = hn + (size_t)BATCH * HID;
    float* stackn = cn + (size_t)BATCH * HID;

    float *sA, *cbuf;
    cudaGetSymbolAddress((void**)&sA, g_stackA);
    cudaGetSymbolAddress((void**)&cbuf, g_c);

    cudaMemcpyAsync(cbuf, c0, sizeof(float) * BATCH * HID, cudaMemcpyDeviceToDevice);
    cudaMemcpyAsync(sA, st0, sizeof(float) * BATCH * SDEP * SWID, cudaMemcpyDeviceToDevice);

    prep_plain<<<4096, 256>>>(W_ih, W_hh);
    prep_swz<<<4096, 256>>>();
    stackrnn_persistent<<<NB, NT>>>(x, h0, b_ih, b_hh, A_w, A_b, D_w, D_b, outs, stackn);

    cudaMemcpyAsync(hn, outs + (size_t)(S_LEN - 1) * BATCH * HID,
                    sizeof(float) * BATCH * HID, cudaMemcpyDeviceToDevice);
    cudaMemcpyAsync(cn, cbuf, sizeof(float) * BATCH * HID, cudaMemcpyDeviceToDevice);
}

// round 4
// speedup vs baseline: 1.2189x; 1.0103x over previous
#include <cuda_runtime.h>
#include <cstdint>
#include <math.h>

#define S_LEN 512
#define BATCH 256
#define IN    256
#define HID   1024
#define SWID  256
#define SDEP  100
#define KTOT  1536
#define IS    (IN + SWID)     // 512
#define NB    128
#define NT    256

// ---------------- scratch (no allocations allowed) ----------------
__device__ __align__(16) float g_stackA[BATCH * SDEP * SWID];   // 26.2 MB
__device__ __align__(16) float g_stackB[BATCH * SDEP * SWID];   // 26.2 MB (also prep scratch)
__device__ __align__(16) float g_Wf[4 * HID * KTOT];            // 25.2 MB frag-ordered weights
__device__ __align__(16) float g_c[BATCH * HID];
__device__ __align__(16) float g_d[2 * BATCH * SWID];
__device__ float g_ctl[2 * BATCH * 3];
__device__ unsigned g_cnt;
__device__ volatile unsigned g_gen;

// ---------------- helpers ----------------
__device__ __forceinline__ float ftf32(float x) {
    float y;
    asm("cvt.rna.tf32.f32 %0, %1;" : "=f"(y) : "f"(x));
    return y;
}

__device__ __forceinline__ void mma_tf32(float c[4], const uint32_t a[4], const uint32_t b[2]) {
    asm volatile(
        "mma.sync.aligned.m16n8k8.row.col.f32.tf32.tf32.f32 "
        "{%0,%1,%2,%3}, {%4,%5,%6,%7}, {%8,%9}, {%0,%1,%2,%3};\n"
        : "+f"(c[0]), "+f"(c[1]), "+f"(c[2]), "+f"(c[3])
        : "r"(a[0]), "r"(a[1]), "r"(a[2]), "r"(a[3]), "r"(b[0]), "r"(b[1]));
}

// ---------------- software grid barrier ----------------
__device__ __forceinline__ void bar_arrive(unsigned* myGen) {
    __syncthreads();
    if (threadIdx.x == 0) {
        unsigned my = g_gen;
        __threadfence();
        unsigned a = atomicAdd(&g_cnt, 1u);
        if (a == NB - 1) {
            g_cnt = 0;
            __threadfence();
            g_gen = my + 1;
        }
        *myGen = my;
    }
}
__device__ __forceinline__ void bar_wait(unsigned myGen) {
    if (threadIdx.x == 0) {
        while (g_gen == myGen) { }
        __threadfence();
    }
    __syncthreads();
}
__device__ __forceinline__ void gbar() {
    unsigned m;
    bar_arrive(&m);
    bar_wait(m);
}

// ---------------- stack blend ----------------
__device__ __forceinline__ void blend_range(
    const float* __restrict__ Sp, float* __restrict__ So,
    const float* __restrict__ dbuf, const float* __restrict__ ctlbuf,
    int is_t0, int bid, int tid)
{
    const float4* sin4  = (const float4*)Sp;
    float4*       sout4 = (float4*)So;
    const float4* d4    = (const float4*)dbuf;
    const int per_blk = (BATCH * SDEP * (SWID / 4)) / NB;   // 12800
    for (int ii = tid; ii < per_blk; ii += NT) {
        const int idx = bid * per_blk + ii;
        const int w4   = idx & 63;
        const int jrow = (idx >> 6) % SDEP;
        const int b    = idx / (SDEP * 64);
        const int base = b * SDEP * 64;
        float4 cur = sin4[base + jrow * 64 + w4];
        float4 o;
        if (is_t0) {
            o = cur;
        } else {
            const float pu = ctlbuf[b * 3 + 0];
            const float po = ctlbuf[b * 3 + 1];
            const float nn = ctlbuf[b * 3 + 2];
            float4 up = (jrow == 0) ? d4[b * 64 + w4] : sin4[base + (jrow - 1) * 64 + w4];
            float4 dn = make_float4(0.f, 0.f, 0.f, 0.f);
            if (jrow < SDEP - 1) dn = sin4[base + (jrow + 1) * 64 + w4];
            o.x = nn * cur.x + pu * up.x + po * dn.x;
            o.y = nn * cur.y + pu * up.y + po * dn.y;
            o.z = nn * cur.z + pu * up.z + po * dn.z;
            o.w = nn * cur.w + pu * up.w + po * dn.w;
        }
        sout4[idx] = o;
    }
}

// ---------------- prep: fused plain weights (tf32), then frag-swizzle ----------------
__global__ void prep_plain(const float* __restrict__ W_ih, const float* __restrict__ W_hh) {
    const int total = 4 * HID * KTOT;
    for (int idx = blockIdx.x * blockDim.x + threadIdx.x; idx < total;
         idx += gridDim.x * blockDim.x) {
        int row = idx / KTOT, k = idx - row * KTOT;
        float v = (k < IS) ? W_ih[(size_t)row * IS + k]
                           : W_hh[(size_t)row * HID + (k - IS)];
        g_stackB[idx] = ftf32(v);
    }
}
// g_Wf layout: idx = ((((jt*8+wj)*2+nf)*48 + kc)*32 + lane)*8 + w ; w = ks*2+p
// value = Wplain[row(n)][k], n = wj*16+nf*8+gid, row(n) = (n>>5)*HID + jt*32 + (n&31),
// k = kc*32 + ks*8 + tig + 4p
__global__ void prep_swz() {
    const int total = 4 * HID * KTOT;
    for (int idx = blockIdx.x * blockDim.x + threadIdx.x; idx < total;
         idx += gridDim.x * blockDim.x) {
        int w    = idx & 7;
        int lane = (idx >> 3) & 31;
        int kc   = (idx >> 8) % 48;
        int t1   = idx / (48 * 256);
        int nf = t1 & 1, wjj = (t1 >> 1) & 7, jt = t1 >> 4;
        int gid = lane >> 2, tig = lane & 3, ks = w >> 1, p = w & 1;
        int n   = wjj * 16 + nf * 8 + gid;
        int row = (n >> 5) * HID + jt * 32 + (n & 31);
        int k   = kc * 32 + ks * 8 + tig + 4 * p;
        g_Wf[idx] = g_stackB[(size_t)row * KTOT + k];
    }
}

// ---------------- the persistent kernel ----------------
__global__ __launch_bounds__(NT, 1) void stackrnn_persistent(
    const float* __restrict__ x,      // [S, B, IN]
    const float* __restrict__ h0,
    const float* __restrict__ b_ih,
    const float* __restrict__ b_hh,
    const float* __restrict__ A_w,
    const float* __restrict__ A_b,
    const float* __restrict__ D_w,
    const float* __restrict__ D_b,
    float* __restrict__ outs,         // [S, B, H]
    float* __restrict__ stackn)       // [B, SDEP, SWID]
{
    // sm is multi-use: GEMM A tiles (2 x 64 x 36 = 4608 floats),
    // epilogue Cs (64 x 132 = 8448), phase-2 As2/Bs2 (2 x 32 x 36)
    __shared__ __align__(16) float sm[8448];

    const int bid = blockIdx.x;
    const int tid = threadIdx.x;
    const int wj = tid >> 5, lane = tid & 31;
    const int gid = lane >> 2, tig = lane & 3;
    const int jt = bid & 31, mt = bid >> 5, bm0 = mt * 64;
    const int arow = tid >> 3;          // 0..31
    const int kl   = (tid & 7) << 2;    // 0,4,...,28
    const int j0 = jt * 32;

    for (int t = 0; t < S_LEN; t++) {
        const float* x_t    = x + (size_t)t * BATCH * IN;
        const float* h_prev = t ? outs + (size_t)(t - 1) * BATCH * HID : h0;
        float*       h_out  = outs + (size_t)t * BATCH * HID;
        const float* Sp = (t & 1) ? g_stackB : g_stackA;
        float*       So = (t & 1) ? g_stackA : g_stackB;
        const float* dprev   = g_d   + ((t + 1) & 1) * (BATCH * SWID);
        const float* ctlprev = g_ctl + ((t + 1) & 1) * (BATCH * 3);
        float*       dcur    = g_d   + (t & 1) * (BATCH * SWID);
        float*       ctlcur  = g_ctl + (t & 1) * (BATCH * 3);

        float pu0 = 0.f, po0 = 0.f, nn0 = 1.f, pu1 = 0.f, po1 = 0.f, nn1 = 1.f;
        if (t) {
            const int b0r = bm0 + arow, b1r = b0r + 32;
            pu0 = ctlprev[b0r * 3 + 0]; po0 = ctlprev[b0r * 3 + 1]; nn0 = ctlprev[b0r * 3 + 2];
            pu1 = ctlprev[b1r * 3 + 0]; po1 = ctlprev[b1r * 3 + 1]; nn1 = ctlprev[b1r * 3 + 2];
        }

        auto ldgA = [&](int kc, float4* v) {
            const int kk = kc * 32 + kl;
#pragma unroll
            for (int rr = 0; rr < 2; rr++) {
                const int b = bm0 + arow + rr * 32;
                float4 q;
                if (kk < IN) {
                    q = *(const float4*)(x_t + (size_t)b * IN + kk);
                } else if (kk < IS) {
                    const int w = kk - IN;
                    float4 s0 = *(const float4*)(Sp + (size_t)b * (SDEP * SWID) + w);
                    if (t == 0) {
                        q = s0;
                    } else {
                        float4 s1 = *(const float4*)(Sp + (size_t)b * (SDEP * SWID) + SWID + w);
                        float4 dv = *(const float4*)(dprev + (size_t)b * SWID + w);
                        const float pu = rr ? pu1 : pu0;
                        const float po = rr ? po1 : po0;
                        const float nn = rr ? nn1 : nn0;
                        q.x = nn * s0.x + pu * dv.x + po * s1.x;
                        q.y = nn * s0.y + pu * dv.y + po * s1.y;
                        q.z = nn * s0.z + pu * dv.z + po * s1.z;
                        q.w = nn * s0.w + pu * dv.w + po * s1.w;
                    }
                } else {
                    q = *(const float4*)(h_prev + (size_t)b * HID + (kk - IS));
                }
                v[rr] = q;
            }
        };
        auto stsA = [&](int buf, const float4* v) {
#pragma unroll
            for (int rr = 0; rr < 2; rr++) {
                const int m = arow + rr * 32;
                float* p = &sm[buf * 2304 + m * 36 + kl];
                p[0] = ftf32(v[rr].x); p[1] = ftf32(v[rr].y);
                p[2] = ftf32(v[rr].z); p[3] = ftf32(v[rr].w);
            }
        };
        auto ldgB = [&](int kc, float4 bb[2][2]) {
#pragma unroll
            for (int nf = 0; nf < 2; nf++) {
                const float4* p = (const float4*)(g_Wf +
                    ((size_t)(((jt * 8 + wj) * 2 + nf) * 48 + kc) * 32 + lane) * 8);
                bb[nf][0] = p[0];
                bb[nf][1] = p[1];
            }
        };

        // ---- phase 1: gates GEMM, warp = 64m x 16n (mf=4, nf=2), no B dup ----
        float acc[4][2][4];
#pragma unroll
        for (int mf = 0; mf < 4; mf++)
#pragma unroll
            for (int nf = 0; nf < 2; nf++)
#pragma unroll
                for (int cc = 0; cc < 4; cc++) acc[mf][nf][cc] = 0.f;

        float4 vA[2], bCur[2][2], bNxt[2][2];
        ldgA(0, vA);
        ldgB(0, bCur);
        stsA(0, vA);
        for (int kc = 0; kc < 48; kc++) {
            const int cur = kc & 1;
            if (kc < 47) { ldgA(kc + 1, vA); ldgB(kc + 1, bNxt); }
            __syncthreads();
#pragma unroll
            for (int ks = 0; ks < 4; ks++) {
                const int k0 = ks * 8;
                uint32_t a[4][4];
#pragma unroll
                for (int mf = 0; mf < 4; mf++) {
                    const float* base = &sm[cur * 2304 + (mf * 16 + gid) * 36 + k0];
                    a[mf][0] = __float_as_uint(base[tig]);
                    a[mf][1] = __float_as_uint(base[8 * 36 + tig]);
                    a[mf][2] = __float_as_uint(base[tig + 4]);
                    a[mf][3] = __float_as_uint(base[8 * 36 + tig + 4]);
                }
#pragma unroll
                for (int nf = 0; nf < 2; nf++) {
                    float2 s;
                    if (ks == 0)      s = make_float2(bCur[nf][0].x, bCur[nf][0].y);
                    else if (ks == 1) s = make_float2(bCur[nf][0].z, bCur[nf][0].w);
                    else if (ks == 2) s = make_float2(bCur[nf][1].x, bCur[nf][1].y);
                    else              s = make_float2(bCur[nf][1].z, bCur[nf][1].w);
                    uint32_t bf[2] = {__float_as_uint(s.x), __float_as_uint(s.y)};
#pragma unroll
                    for (int mf = 0; mf < 4; mf++) mma_tf32(acc[mf][nf], a[mf], bf);
                }
            }
            if (kc < 47) {
                stsA(cur ^ 1, vA);
#pragma unroll
                for (int nf = 0; nf < 2; nf++) {
                    bCur[nf][0] = bNxt[nf][0];
                    bCur[nf][1] = bNxt[nf][1];
                }
            }
        }
        __syncthreads();   // As region dead; reuse as Cs[64][132]

        // scatter acc -> Cs
#pragma unroll
        for (int mf = 0; mf < 4; mf++)
#pragma unroll
            for (int nf = 0; nf < 2; nf++)
#pragma unroll
                for (int cc = 0; cc < 4; cc++) {
                    const int m   = mf * 16 + ((cc >> 1) << 3) + gid;
                    const int col = wj * 16 + nf * 8 + (tig << 1) + (cc & 1);
                    sm[m * 132 + col] = acc[mf][nf][cc];
                }
        __syncthreads();

        // LSTM pointwise: thread -> (row m = tid>>2, 8 cols jb..jb+7)
        {
            const int m  = tid >> 2;
            const int jb = (tid & 3) << 3;
            const int b  = bm0 + m;
            const size_t off = (size_t)b * HID + j0 + jb;
            float GI[8], GF[8], GG[8], GO[8], CC[8], HH[8];
            *(float4*)&GI[0] = *(float4*)&sm[m * 132 + jb];
            *(float4*)&GI[4] = *(float4*)&sm[m * 132 + jb + 4];
            *(float4*)&GF[0] = *(float4*)&sm[m * 132 + 32 + jb];
            *(float4*)&GF[4] = *(float4*)&sm[m * 132 + 32 + jb + 4];
            *(float4*)&GG[0] = *(float4*)&sm[m * 132 + 64 + jb];
            *(float4*)&GG[4] = *(float4*)&sm[m * 132 + 64 + jb + 4];
            *(float4*)&GO[0] = *(float4*)&sm[m * 132 + 96 + jb];
            *(float4*)&GO[4] = *(float4*)&sm[m * 132 + 96 + jb + 4];
            *(float4*)&CC[0] = *(float4*)(g_c + off);
            *(float4*)&CC[4] = *(float4*)(g_c + off + 4);
#pragma unroll
            for (int e = 0; e < 8; e++) {
                const int jg = j0 + jb + e;
                float gi = GI[e] + b_ih[jg]           + b_hh[jg];
                float gf = GF[e] + b_ih[HID + jg]     + b_hh[HID + jg];
                float gg = GG[e] + b_ih[2 * HID + jg] + b_hh[2 * HID + jg];
                float go = GO[e] + b_ih[3 * HID + jg] + b_hh[3 * HID + jg];
                float iv = 1.f / (1.f + expf(-gi));
                float fv = 1.f / (1.f + expf(-gf));
                float gv = tanhf(gg);
                float ov = 1.f / (1.f + expf(-go));
                float cn_ = fv * CC[e] + iv * gv;
                CC[e] = cn_;
                HH[e] = ov * tanhf(cn_);
            }
            *(float4*)(g_c + off)     = *(float4*)&CC[0];
            *(float4*)(g_c + off + 4) = *(float4*)&CC[4];
            *(float4*)(h_out + off)     = *(float4*)&HH[0];
            *(float4*)(h_out + off + 4) = *(float4*)&HH[4];
        }

        // ---- barrier A (split): blend overlaps the wait ----
        unsigned myg;
        bar_arrive(&myg);
        blend_range(Sp, So, dprev, ctlprev, t == 0, bid, tid);
        bar_wait(myg);

        // ---- phase 2: d = tanh(h @ D_w^T + D_b); controls softmax ----
        if (bid < 64) {
            const int bx = bid & 7, by = bid >> 3;
            const int w0 = bx * 32, bm0d = by * 32;
            const int wm2 = (tid >> 5) >> 2, wn2 = (tid >> 5) & 3;
            float acc2[4] = {0.f, 0.f, 0.f, 0.f};
            for (int kc = 0; kc < HID; kc += 32) {
                const int kk = kc + kl;
                {
                    float4 v = *(const float4*)(h_out + (size_t)(bm0d + arow) * HID + kk);
                    float* p = &sm[arow * 36 + kl];
                    p[0] = ftf32(v.x); p[1] = ftf32(v.y); p[2] = ftf32(v.z); p[3] = ftf32(v.w);
                }
                {
                    float4 v = *(const float4*)(D_w + (size_t)(w0 + arow) * HID + kk);
                    float* p = &sm[1152 + arow * 36 + kl];
                    p[0] = ftf32(v.x); p[1] = ftf32(v.y); p[2] = ftf32(v.z); p[3] = ftf32(v.w);
                }
                __syncthreads();
#pragma unroll
                for (int ks = 0; ks < 4; ks++) {
                    const int k0 = ks * 8;
                    uint32_t a[4], bf[2];
                    const int m0 = wm2 * 16;
                    a[0] = __float_as_uint(sm[(m0 + gid) * 36 + k0 + tig]);
                    a[1] = __float_as_uint(sm[(m0 + 8 + gid) * 36 + k0 + tig]);
                    a[2] = __float_as_uint(sm[(m0 + gid) * 36 + k0 + tig + 4]);
                    a[3] = __float_as_uint(sm[(m0 + 8 + gid) * 36 + k0 + tig + 4]);
                    const int n0 = wn2 * 8;
                    bf[0] = __float_as_uint(sm[1152 + (n0 + gid) * 36 + k0 + tig]);
                    bf[1] = __float_as_uint(sm[1152 + (n0 + gid) * 36 + k0 + tig + 4]);
                    mma_tf32(acc2, a, bf);
                }
                __syncthreads();
            }
#pragma unroll
            for (int cc = 0; cc < 4; cc++) {
                const int row = wm2 * 16 + ((cc >> 1) << 3) + gid;
                const int col = wn2 * 8 + (tig << 1) + (cc & 1);
                dcur[(size_t)(bm0d + row) * SWID + w0 + col] = tanhf(acc2[cc] + D_b[w0 + col]);
            }
        } else if (bid < 72) {
            const int warp = tid >> 5;
            const int bm0c = (bid - 64) * 32;
            for (int q = 0; q < 4; q++) {
                const int b = bm0c + warp * 4 + q;
                float s0 = 0.f, s1 = 0.f, s2 = 0.f;
                for (int k = lane; k < HID; k += 32) {
                    float hv = h_out[(size_t)b * HID + k];
                    s0 += hv * A_w[k];
                    s1 += hv * A_w[HID + k];
                    s2 += hv * A_w[2 * HID + k];
                }
#pragma unroll
                for (int o = 16; o > 0; o >>= 1) {
                    s0 += __shfl_xor_sync(0xffffffffu, s0, o);
                    s1 += __shfl_xor_sync(0xffffffffu, s1, o);
                    s2 += __shfl_xor_sync(0xffffffffu, s2, o);
                }
                if (lane == 0) {
                    s0 += A_b[0]; s1 += A_b[1]; s2 += A_b[2];
                    float mx = fmaxf(s0, fmaxf(s1, s2));
                    float e0 = expf(s0 - mx), e1 = expf(s1 - mx), e2 = expf(s2 - mx);
                    float inv = 1.f / (e0 + e1 + e2);
                    ctlcur[b * 3 + 0] = e0 * inv;
                    ctlcur[b * 3 + 1] = e1 * inv;
                    ctlcur[b * 3 + 2] = e2 * inv;
                }
            }
        }
        gbar();   // d_t / ctl_t / stack visible for step t+1
    }

    // ---- final stack: R_512 = blend(R_511, d_511, ctl_511) -> stackn ----
    blend_range(g_stackA, stackn, g_d + BATCH * SWID, g_ctl + BATCH * 3, 0, bid, tid);
}

// ---------------- launch ----------------
extern "C" void kernel_launch(void* const* d_in, const int* in_sizes, int n_in,
                              void* d_out, int out_size)
{
    const float* x    = (const float*)d_in[0];
    const float* h0   = (const float*)d_in[1];
    const float* c0   = (const float*)d_in[2];
    const float* st0  = (const float*)d_in[3];
    const float* W_ih = (const float*)d_in[4];
    const float* W_hh = (const float*)d_in[5];
    const float* b_ih = (const float*)d_in[6];
    const float* b_hh = (const float*)d_in[7];
    const float* A_w  = (const float*)d_in[8];
    const float* A_b  = (const float*)d_in[9];
    const float* D_w  = (const float*)d_in[10];
    const float* D_b  = (const float*)d_in[11];

    float* out    = (float*)d_out;
    float* outs   = out;
    float* hn     = outs + (size_t)S_LEN * BATCH * HID;
    float* cn     = hn + (size_t)BATCH * HID;
    float* stackn = cn + (size_t)BATCH * HID;

    float *sA, *cbuf;
    cudaGetSymbolAddress((void**)&sA, g_stackA);
    cudaGetSymbolAddress((void**)&cbuf, g_c);

    cudaMemcpyAsync(cbuf, c0, sizeof(float) * BATCH * HID, cudaMemcpyDeviceToDevice);
    cudaMemcpyAsync(sA, st0, sizeof(float) * BATCH * SDEP * SWID, cudaMemcpyDeviceToDevice);

    prep_plain<<<4096, 256>>>(W_ih, W_hh);
    prep_swz<<<4096, 256>>>();
    stackrnn_persistent<<<NB, NT>>>(x, h0, b_ih, b_hh, A_w, A_b, D_w, D_b, outs, stackn);

    cudaMemcpyAsync(hn, outs + (size_t)(S_LEN - 1) * BATCH * HID,
                    sizeof(float) * BATCH * HID, cudaMemcpyDeviceToDevice);
    cudaMemcpyAsync(cn, cbuf, sizeof(float) * BATCH * HID, cudaMemcpyDeviceToDevice);
}

// round 6
// speedup vs baseline: 1.4288x; 1.1722x over previous
#include <cuda_runtime.h>
#include <cstdint>
#include <math.h>

#define S_LEN 512
#define BATCH 256
#define IN    256
#define HID   1024
#define SWID  256
#define SDEP  100
#define KTOT  1536
#define IS    (IN + SWID)     // 512
#define NB    128
#define NT    512

#define BUFSZ 2112            // 4 mt * 4 ks * 132

// ---------------- scratch (no allocations allowed) ----------------
__device__ __align__(16) float g_stackA[BATCH * SDEP * SWID];   // 26.2 MB
__device__ __align__(16) float g_stackB[BATCH * SDEP * SWID];   // 26.2 MB (also prep scratch)
__device__ __align__(16) float g_Wf[4 * HID * KTOT];            // 25.2 MB frag-ordered weights
__device__ __align__(16) float g_bias[4 * HID];
__device__ __align__(16) float g_c[BATCH * HID];
__device__ __align__(16) float g_d[2 * BATCH * SWID];
__device__ float g_ctl[2 * BATCH * 3];
__device__ unsigned g_cnt;
__device__ volatile unsigned g_gen;

// ---------------- helpers ----------------
__device__ __forceinline__ float ftf32(float x) {
    float y;
    asm("cvt.rna.tf32.f32 %0, %1;" : "=f"(y) : "f"(x));
    return y;
}

__device__ __forceinline__ void mma_tf32(float c[4], const uint32_t a[4], const uint32_t b[2]) {
    asm volatile(
        "mma.sync.aligned.m16n8k8.row.col.f32.tf32.tf32.f32 "
        "{%0,%1,%2,%3}, {%4,%5,%6,%7}, {%8,%9}, {%0,%1,%2,%3};\n"
        : "+f"(c[0]), "+f"(c[1]), "+f"(c[2]), "+f"(c[3])
        : "r"(a[0]), "r"(a[1]), "r"(a[2]), "r"(a[3]), "r"(b[0]), "r"(b[1]));
}

// ---------------- software grid barrier ----------------
__device__ __forceinline__ void bar_arrive(unsigned* myGen) {
    __syncthreads();
    if (threadIdx.x == 0) {
        unsigned my = g_gen;
        __threadfence();
        unsigned a = atomicAdd(&g_cnt, 1u);
        if (a == NB - 1) {
            g_cnt = 0;
            __threadfence();
            g_gen = my + 1;
        }
        *myGen = my;
    }
}
__device__ __forceinline__ void bar_wait(unsigned myGen) {
    if (threadIdx.x == 0) {
        while (g_gen == myGen) { }
        __threadfence();
    }
    __syncthreads();
}

// ---------------- stack blend ----------------
__device__ __forceinline__ void blend_range(
    const float* __restrict__ Sp, float* __restrict__ So,
    const float* __restrict__ dbuf, const float* __restrict__ ctlbuf,
    int is_t0, int bid, int tid)
{
    const float4* sin4  = (const float4*)Sp;
    float4*       sout4 = (float4*)So;
    const float4* d4    = (const float4*)dbuf;
    const int per_blk = (BATCH * SDEP * (SWID / 4)) / NB;   // 12800
    for (int ii = tid; ii < per_blk; ii += NT) {
        const int idx = bid * per_blk + ii;
        const int w4   = idx & 63;
        const int jrow = (idx >> 6) % SDEP;
        const int b    = idx / (SDEP * 64);
        const int base = b * SDEP * 64;
        float4 cur = sin4[base + jrow * 64 + w4];
        float4 o;
        if (is_t0) {
            o = cur;
        } else {
            const float pu = ctlbuf[b * 3 + 0];
            const float po = ctlbuf[b * 3 + 1];
            const float nn = ctlbuf[b * 3 + 2];
            float4 up = (jrow == 0) ? d4[b * 64 + w4] : sin4[base + (jrow - 1) * 64 + w4];
            float4 dn = make_float4(0.f, 0.f, 0.f, 0.f);
            if (jrow < SDEP - 1) dn = sin4[base + (jrow + 1) * 64 + w4];
            o.x = nn * cur.x + pu * up.x + po * dn.x;
            o.y = nn * cur.y + pu * up.y + po * dn.y;
            o.z = nn * cur.z + pu * up.z + po * dn.z;
            o.w = nn * cur.w + pu * up.w + po * dn.w;
        }
        sout4[idx] = o;
    }
}

// ---------------- prep kernels ----------------
__global__ void prep_plain(const float* __restrict__ W_ih, const float* __restrict__ W_hh,
                           const float* __restrict__ b_ih, const float* __restrict__ b_hh) {
    const int total = 4 * HID * KTOT;
    for (int idx = blockIdx.x * blockDim.x + threadIdx.x; idx < total;
         idx += gridDim.x * blockDim.x) {
        int row = idx / KTOT, k = idx - row * KTOT;
        float v = (k < IS) ? W_ih[(size_t)row * IS + k]
                           : W_hh[(size_t)row * HID + (k - IS)];
        g_stackB[idx] = ftf32(v);
    }
    for (int i = blockIdx.x * blockDim.x + threadIdx.x; i < 4 * HID;
         i += gridDim.x * blockDim.x)
        g_bias[i] = b_ih[i] + b_hh[i];
}
// g_Wf layout: idx = ((((jt*4+wn)*4+g)*48 + kc)*32 + lane)*8 + w ; w = ks*2+p
// value = Wplain[row][k], row = g*HID + jt*32 + wn*8 + (lane>>2),
// k = kc*32 + ks*8 + (lane&3) + 4p
__global__ void prep_swz() {
    const int total = 4 * HID * KTOT;
    for (int idx = blockIdx.x * blockDim.x + threadIdx.x; idx < total;
         idx += gridDim.x * blockDim.x) {
        int w    = idx & 7;
        int lane = (idx >> 3) & 31;
        int kc   = (idx >> 8) % 48;
        int t1   = idx / (48 * 256);
        int g = t1 & 3, wn = (t1 >> 2) & 3, jt = t1 >> 4;
        int gid = lane >> 2, tig = lane & 3, ks = w >> 1, p = w & 1;
        int row = g * HID + jt * 32 + wn * 8 + gid;
        int k   = kc * 32 + ks * 8 + tig + 4 * p;
        g_Wf[idx] = g_stackB[(size_t)row * KTOT + k];
    }
}

// ---------------- the persistent kernel ----------------
__global__ __launch_bounds__(NT) void stackrnn_persistent(
    const float* __restrict__ x,      // [S, B, IN]
    const float* __restrict__ h0,
    const float* __restrict__ A_w,
    const float* __restrict__ A_b,
    const float* __restrict__ D_w,
    const float* __restrict__ D_b,
    float* __restrict__ outs,         // [S, B, H]
    float* __restrict__ stackn)       // [B, SDEP, SWID]
{
    // sm usage: GEMM A frag buffers 2 x BUFSZ = 4224 floats; phase-2 As2/Bs2 (2304) alias
    __shared__ __align__(16) float sm[2 * BUFSZ];

    const int bid = blockIdx.x;
    const int tid = threadIdx.x;
    const int warp = tid >> 5, lane = tid & 31;
    const int wm = warp >> 2, wn = warp & 3;        // 4m x 4n warps
    const int gi_r = lane >> 2, tig = lane & 3;
    const int jt = bid & 31, mt = bid >> 5, bm0 = mt * 64;
    const int j0 = jt * 32;

    // A loader role: thread -> row lr (0..63), k-offset lk
    const int lr = tid >> 3;            // 0..63
    const int lk = (tid & 7) << 2;      // 0,4,...,28
    const int lb = bm0 + lr;
    // frag-scatter constants for stsA
    const int s_mt  = lr >> 4;
    const int s_gid = lr & 7;
    const int s_hi  = (lr >> 3) & 1;
    const int s_ks  = lk >> 3;
    const int s_q   = (lk >> 2) & 1;
    const int s_w   = s_hi + 2 * s_q;
    const int s_off = (s_mt * 4 + s_ks) * 132 + (s_gid * 4) * 4 + s_w;

    for (int t = 0; t < S_LEN; t++) {
        const float* x_t    = x + (size_t)t * BATCH * IN;
        const float* h_prev = t ? outs + (size_t)(t - 1) * BATCH * HID : h0;
        float*       h_out  = outs + (size_t)t * BATCH * HID;
        const float* Sp = (t & 1) ? g_stackB : g_stackA;
        float*       So = (t & 1) ? g_stackA : g_stackB;
        const float* dprev   = g_d   + ((t + 1) & 1) * (BATCH * SWID);
        const float* ctlprev = g_ctl + ((t + 1) & 1) * (BATCH * 3);
        float*       dcur    = g_d   + (t & 1) * (BATCH * SWID);
        float*       ctlcur  = g_ctl + (t & 1) * (BATCH * 3);

        float cpu = 0.f, cpo = 0.f, cnn = 1.f;
        if (t) {
            cpu = ctlprev[lb * 3 + 0];
            cpo = ctlprev[lb * 3 + 1];
            cnn = ctlprev[lb * 3 + 2];
        }

        auto ldgA = [&](int kc) -> float4 {
            const int kk = kc * 32 + lk;
            if (kk < IN) {
                return *(const float4*)(x_t + (size_t)lb * IN + kk);
            } else if (kk < IS) {
                const int w = kk - IN;
                const float* sb = Sp + (size_t)lb * (SDEP * SWID);
                float4 s0 = *(const float4*)(sb + w);
                if (t == 0) return s0;
                float4 s1 = *(const float4*)(sb + SWID + w);
                float4 dv = *(const float4*)(dprev + (size_t)lb * SWID + w);
                float4 v;
                v.x = cnn * s0.x + cpu * dv.x + cpo * s1.x;
                v.y = cnn * s0.y + cpu * dv.y + cpo * s1.y;
                v.z = cnn * s0.z + cpu * dv.z + cpo * s1.z;
                v.w = cnn * s0.w + cpu * dv.w + cpo * s1.w;
                return v;
            } else {
                return *(const float4*)(h_prev + (size_t)lb * HID + (kk - IS));
            }
        };
        auto stsA = [&](int buf, float4 v) {
            float* p = &sm[buf * BUFSZ + s_off];
            p[0]  = ftf32(v.x);
            p[4]  = ftf32(v.y);
            p[8]  = ftf32(v.z);
            p[12] = ftf32(v.w);
        };
        auto ldgB = [&](int kc, float4 bb[4][2]) {
#pragma unroll
            for (int g = 0; g < 4; g++) {
                const float4* p = (const float4*)(g_Wf +
                    (size_t)(((jt * 4 + wn) * 4 + g) * 48 + kc) * 256 + lane * 8);
                bb[g][0] = p[0];
                bb[g][1] = p[1];
            }
        };

        // ---- phase 1: gates GEMM, warp = 16m x (4 gates x 8j) ----
        float acc[4][4];
#pragma unroll
        for (int g = 0; g < 4; g++)
#pragma unroll
            for (int cc = 0; cc < 4; cc++) acc[g][cc] = 0.f;

        float4 vN;
        float4 bC[4][2], bN[4][2];
        vN = ldgA(0);
        ldgB(0, bC);
        stsA(0, vN);
        for (int kc = 0; kc < 48; kc++) {
            const int cur = kc & 1;
            if (kc < 47) { vN = ldgA(kc + 1); ldgB(kc + 1, bN); }
            __syncthreads();
#pragma unroll
            for (int ks = 0; ks < 4; ks++) {
                const float4 af = *(const float4*)&sm[cur * BUFSZ + (wm * 4 + ks) * 132 + lane * 4];
                uint32_t a[4] = {__float_as_uint(af.x), __float_as_uint(af.y),
                                 __float_as_uint(af.z), __float_as_uint(af.w)};
#pragma unroll
                for (int g = 0; g < 4; g++) {
                    float2 s;
                    if (ks == 0)      s = make_float2(bC[g][0].x, bC[g][0].y);
                    else if (ks == 1) s = make_float2(bC[g][0].z, bC[g][0].w);
                    else if (ks == 2) s = make_float2(bC[g][1].x, bC[g][1].y);
                    else              s = make_float2(bC[g][1].z, bC[g][1].w);
                    uint32_t bf[2] = {__float_as_uint(s.x), __float_as_uint(s.y)};
                    mma_tf32(acc[g], a, bf);
                }
            }
            if (kc < 47) {
                stsA(cur ^ 1, vN);
#pragma unroll
                for (int g = 0; g < 4; g++) {
                    bC[g][0] = bN[g][0];
                    bC[g][1] = bN[g][1];
                }
            }
        }

        // ---- LSTM pointwise epilogue, direct from registers ----
        {
            const int jb = j0 + wn * 8 + (tig << 1);
            const float2 B0 = *(const float2*)(g_bias + jb);
            const float2 B1 = *(const float2*)(g_bias + HID + jb);
            const float2 B2 = *(const float2*)(g_bias + 2 * HID + jb);
            const float2 B3 = *(const float2*)(g_bias + 3 * HID + jb);
#pragma unroll
            for (int cc = 0; cc < 4; cc++) {
                const int row = wm * 16 + ((cc >> 1) << 3) + gi_r;
                const int b = bm0 + row;
                const int odd = cc & 1;
                const size_t off = (size_t)b * HID + jb + odd;
                float gi = acc[0][cc] + (odd ? B0.y : B0.x);
                float gf = acc[1][cc] + (odd ? B1.y : B1.x);
                float gg = acc[2][cc] + (odd ? B2.y : B2.x);
                float go = acc[3][cc] + (odd ? B3.y : B3.x);
                float iv = 1.f / (1.f + expf(-gi));
                float fv = 1.f / (1.f + expf(-gf));
                float gv = tanhf(gg);
                float ov = 1.f / (1.f + expf(-go));
                float cn_ = fv * g_c[off] + iv * gv;
                g_c[off]  = cn_;
                h_out[off] = ov * tanhf(cn_);
            }
        }

        // ---- barrier A (split): blend overlaps the wait ----
        unsigned myg;
        bar_arrive(&myg);
        blend_range(Sp, So, dprev, ctlprev, t == 0, bid, tid);
        bar_wait(myg);

        // ---- phase 2: d = tanh(h @ D_w^T + D_b); controls softmax ----
        if (bid < 64) {
            const int bx = bid & 7, by = bid >> 3;
            const int w0 = bx * 32, bm0d = by * 32;
            const int wm2 = warp >> 2, wn2 = warp & 3;
            const int arow = tid >> 3;          // valid for tid < 256
            const int kl   = (tid & 7) << 2;
            float acc2[4] = {0.f, 0.f, 0.f, 0.f};
            for (int kc = 0; kc < HID; kc += 32) {
                if (tid < 256) {
                    const int kk = kc + kl;
                    {
                        float4 v = *(const float4*)(h_out + (size_t)(bm0d + arow) * HID + kk);
                        float* p = &sm[arow * 36 + kl];
                        p[0] = ftf32(v.x); p[1] = ftf32(v.y); p[2] = ftf32(v.z); p[3] = ftf32(v.w);
                    }
                    {
                        float4 v = *(const float4*)(D_w + (size_t)(w0 + arow) * HID + kk);
                        float* p = &sm[1152 + arow * 36 + kl];
                        p[0] = ftf32(v.x); p[1] = ftf32(v.y); p[2] = ftf32(v.z); p[3] = ftf32(v.w);
                    }
                }
                __syncthreads();
                if (warp < 8) {
#pragma unroll
                    for (int ks = 0; ks < 4; ks++) {
                        const int k0 = ks * 8;
                        uint32_t a[4], bf[2];
                        const int m0 = wm2 * 16;
                        a[0] = __float_as_uint(sm[(m0 + gi_r) * 36 + k0 + tig]);
                        a[1] = __float_as_uint(sm[(m0 + 8 + gi_r) * 36 + k0 + tig]);
                        a[2] = __float_as_uint(sm[(m0 + gi_r) * 36 + k0 + tig + 4]);
                        a[3] = __float_as_uint(sm[(m0 + 8 + gi_r) * 36 + k0 + tig + 4]);
                        const int n0 = wn2 * 8;
                        bf[0] = __float_as_uint(sm[1152 + (n0 + gi_r) * 36 + k0 + tig]);
                        bf[1] = __float_as_uint(sm[1152 + (n0 + gi_r) * 36 + k0 + tig + 4]);
                        mma_tf32(acc2, a, bf);
                    }
                }
                __syncthreads();
            }
            if (warp < 8) {
#pragma unroll
                for (int cc = 0; cc < 4; cc++) {
                    const int row = wm2 * 16 + ((cc >> 1) << 3) + gi_r;
                    const int col = wn2 * 8 + (tig << 1) + (cc & 1);
                    dcur[(size_t)(bm0d + row) * SWID + w0 + col] =
                        tanhf(acc2[cc] + D_b[w0 + col]);
                }
            }
        } else if (bid < 72) {
            const int bm0c = (bid - 64) * 32;
            for (int q = 0; q < 2; q++) {
                const int b = bm0c + warp * 2 + q;
                float s0 = 0.f, s1 = 0.f, s2 = 0.f;
                for (int k = lane; k < HID; k += 32) {
                    float hv = h_out[(size_t)b * HID + k];
                    s0 += hv * A_w[k];
                    s1 += hv * A_w[HID + k];
                    s2 += hv * A_w[2 * HID + k];
                }
#pragma unroll
                for (int o = 16; o > 0; o >>= 1) {
                    s0 += __shfl_xor_sync(0xffffffffu, s0, o);
                    s1 += __shfl_xor_sync(0xffffffffu, s1, o);
                    s2 += __shfl_xor_sync(0xffffffffu, s2, o);
                }
                if (lane == 0) {
                    s0 += A_b[0]; s1 += A_b[1]; s2 += A_b[2];
                    float mx = fmaxf(s0, fmaxf(s1, s2));
                    float e0 = expf(s0 - mx), e1 = expf(s1 - mx), e2 = expf(s2 - mx);
                    float inv = 1.f / (e0 + e1 + e2);
                    ctlcur[b * 3 + 0] = e0 * inv;
                    ctlcur[b * 3 + 1] = e1 * inv;
                    ctlcur[b * 3 + 2] = e2 * inv;
                }
            }
        }
        {
            unsigned m2;
            bar_arrive(&m2);
            bar_wait(m2);
        }
    }

    // ---- final stack: R_512 = blend(R_511, d_511, ctl_511) -> stackn ----
    blend_range(g_stackA, stackn, g_d + BATCH * SWID, g_ctl + BATCH * 3, 0, bid, tid);
}

// ---------------- launch ----------------
extern "C" void kernel_launch(void* const* d_in, const int* in_sizes, int n_in,
                              void* d_out, int out_size)
{
    const float* x    = (const float*)d_in[0];
    const float* h0   = (const float*)d_in[1];
    const float* c0   = (const float*)d_in[2];
    const float* st0  = (const float*)d_in[3];
    const float* W_ih = (const float*)d_in[4];
    const float* W_hh = (const float*)d_in[5];
    const float* b_ih = (const float*)d_in[6];
    const float* b_hh = (const float*)d_in[7];
    const float* A_w  = (const float*)d_in[8];
    const float* A_b  = (const float*)d_in[9];
    const float* D_w  = (const float*)d_in[10];
    const float* D_b  = (const float*)d_in[11];

    float* out    = (float*)d_out;
    float* outs   = out;
    float* hn     = outs + (size_t)S_LEN * BATCH * HID;
    float* cn     = hn + (size_t)BATCH * HID;
    float* stackn = cn + (size_t)BATCH * HID;

    float *sA, *cbuf;
    cudaGetSymbolAddress((void**)&sA, g_stackA);
    cudaGetSymbolAddress((void**)&cbuf, g_c);

    cudaMemcpyAsync(cbuf, c0, sizeof(float) * BATCH * HID, cudaMemcpyDeviceToDevice);
    cudaMemcpyAsync(sA, st0, sizeof(float) * BATCH * SDEP * SWID, cudaMemcpyDeviceToDevice);

    prep_plain<<<4096, 256>>>(W_ih, W_hh, b_ih, b_hh);
    prep_swz<<<4096, 256>>>();
    stackrnn_persistent<<<NB, NT>>>(x, h0, A_w, A_b, D_w, D_b, outs, stackn);

    cudaMemcpyAsync(hn, outs + (size_t)(S_LEN - 1) * BATCH * HID,
                    sizeof(float) * BATCH * HID, cudaMemcpyDeviceToDevice);
    cudaMemcpyAsync(cn, cbuf, sizeof(float) * BATCH * HID, cudaMemcpyDeviceToDevice);
}

// round 7
// speedup vs baseline: 1.4567x; 1.0195x over previous
#include <cuda_runtime.h>
#include <cstdint>
#include <math.h>

#define S_LEN 512
#define BATCH 256
#define IN    256
#define HID   1024
#define SWID  256
#define SDEP  100
#define KTOT  1536
#define IS    (IN + SWID)     // 512
#define NB    128
#define NT    512

#define BUFSZ 2112            // 4 mt * 4 ks * 132

// ---------------- scratch (no allocations allowed) ----------------
__device__ __align__(16) float g_stackA[BATCH * SDEP * SWID];   // 26.2 MB
__device__ __align__(16) float g_stackB[BATCH * SDEP * SWID];   // 26.2 MB (also prep staging)
__device__ __align__(16) float g_Wf[4 * HID * KTOT];            // 25.2 MB frag-ordered weights
__device__ __align__(16) float g_bias[4 * HID];
__device__ __align__(16) float g_c[BATCH * HID];
__device__ __align__(16) float g_d[2 * BATCH * SWID];
__device__ float g_ctl[2 * BATCH * 3];
__device__ unsigned g_cnt;
__device__ volatile unsigned g_gen;

// ---------------- helpers ----------------
__device__ __forceinline__ float ftf32(float x) {
    float y;
    asm("cvt.rna.tf32.f32 %0, %1;" : "=f"(y) : "f"(x));
    return y;
}

__device__ __forceinline__ void mma_tf32(float c[4], const uint32_t a[4], const uint32_t b[2]) {
    asm volatile(
        "mma.sync.aligned.m16n8k8.row.col.f32.tf32.tf32.f32 "
        "{%0,%1,%2,%3}, {%4,%5,%6,%7}, {%8,%9}, {%0,%1,%2,%3};\n"
        : "+f"(c[0]), "+f"(c[1]), "+f"(c[2]), "+f"(c[3])
        : "r"(a[0]), "r"(a[1]), "r"(a[2]), "r"(a[3]), "r"(b[0]), "r"(b[1]));
}

// ---------------- software grid barrier ----------------
__device__ __forceinline__ void bar_arrive(unsigned* myGen) {
    __syncthreads();
    if (threadIdx.x == 0) {
        unsigned my = g_gen;
        __threadfence();
        unsigned a = atomicAdd(&g_cnt, 1u);
        if (a == NB - 1) {
            g_cnt = 0;
            __threadfence();
            g_gen = my + 1;
        }
        *myGen = my;
    }
}
__device__ __forceinline__ void bar_wait(unsigned myGen) {
    if (threadIdx.x == 0) {
        while (g_gen == myGen) { }
        __threadfence();
    }
    __syncthreads();
}
__device__ __forceinline__ void gbar() {
    unsigned m;
    bar_arrive(&m);
    bar_wait(m);
}

// ---------------- stack blend ----------------
__device__ __forceinline__ void blend_range(
    const float* __restrict__ Sp, float* __restrict__ So,
    const float* __restrict__ dbuf, const float* __restrict__ ctlbuf,
    int is_t0, int bid, int tid)
{
    const float4* sin4  = (const float4*)Sp;
    float4*       sout4 = (float4*)So;
    const float4* d4    = (const float4*)dbuf;
    const int per_blk = (BATCH * SDEP * (SWID / 4)) / NB;   // 12800
    for (int ii = tid; ii < per_blk; ii += NT) {
        const int idx = bid * per_blk + ii;
        const int w4   = idx & 63;
        const int jrow = (idx >> 6) % SDEP;
        const int b    = idx / (SDEP * 64);
        const int base = b * SDEP * 64;
        float4 cur = sin4[base + jrow * 64 + w4];
        float4 o;
        if (is_t0) {
            o = cur;
        } else {
            const float pu = ctlbuf[b * 3 + 0];
            const float po = ctlbuf[b * 3 + 1];
            const float nn = ctlbuf[b * 3 + 2];
            float4 up = (jrow == 0) ? d4[b * 64 + w4] : sin4[base + (jrow - 1) * 64 + w4];
            float4 dn = make_float4(0.f, 0.f, 0.f, 0.f);
            if (jrow < SDEP - 1) dn = sin4[base + (jrow + 1) * 64 + w4];
            o.x = nn * cur.x + pu * up.x + po * dn.x;
            o.y = nn * cur.y + pu * up.y + po * dn.y;
            o.z = nn * cur.z + pu * up.z + po * dn.z;
            o.w = nn * cur.w + pu * up.w + po * dn.w;
        }
        sout4[idx] = o;
    }
}

// ---------------- the persistent kernel (prep + 512 steps) ----------------
__global__ __launch_bounds__(NT) void stackrnn_persistent(
    const float* __restrict__ x,      // [S, B, IN]
    const float* __restrict__ h0,
    const float* __restrict__ W_ih,   // [4H, IS]
    const float* __restrict__ W_hh,   // [4H, H]
    const float* __restrict__ b_ih,
    const float* __restrict__ b_hh,
    const float* __restrict__ A_w,
    const float* __restrict__ A_b,
    const float* __restrict__ D_w,
    const float* __restrict__ D_b,
    float* __restrict__ outs,         // [S, B, H]
    float* __restrict__ stackn)       // [B, SDEP, SWID]
{
    __shared__ __align__(16) float sm[2 * BUFSZ];

    const int bid = blockIdx.x;
    const int tid = threadIdx.x;
    const int warp = tid >> 5, lane = tid & 31;
    const int wm = warp >> 2, wn = warp & 3;        // 4m x 4n warps
    const int gi_r = lane >> 2, tig = lane & 3;
    const int jt = bid & 31, mt = bid >> 5, bm0 = mt * 64;
    const int j0 = jt * 32;

    // ======== prep P1: plain tf32 weights -> g_stackB, fused bias ========
    for (int idx = bid * NT + tid; idx < 4 * HID * KTOT; idx += NB * NT) {
        int row = idx / KTOT, k = idx - row * KTOT;
        float v = (k < IS) ? W_ih[(size_t)row * IS + k]
                           : W_hh[(size_t)row * HID + (k - IS)];
        g_stackB[idx] = ftf32(v);
    }
    for (int i = bid * NT + tid; i < 4 * HID; i += NB * NT)
        g_bias[i] = b_ih[i] + b_hh[i];
    gbar();
    // ======== prep P2: frag-swizzle -> g_Wf ========
    // idx = ((((jt*4+wn)*4+g)*48 + kc)*32 + lane)*8 + w ; w = ks*2+p
    for (int idx = bid * NT + tid; idx < 4 * HID * KTOT; idx += NB * NT) {
        int w    = idx & 7;
        int ln   = (idx >> 3) & 31;
        int kc   = (idx >> 8) % 48;
        int t1   = idx / (48 * 256);
        int g = t1 & 3, wnn = (t1 >> 2) & 3, jtt = t1 >> 4;
        int gg = ln >> 2, tt = ln & 3, ks = w >> 1, p = w & 1;
        int row = g * HID + jtt * 32 + wnn * 8 + gg;
        int k   = kc * 32 + ks * 8 + tt + 4 * p;
        g_Wf[idx] = g_stackB[(size_t)row * KTOT + k];
    }
    gbar();

    // A loader role: thread -> row lr (0..63), k-offset lk
    const int lr = tid >> 3;            // 0..63
    const int lk = (tid & 7) << 2;      // 0,4,...,28
    const int lb = bm0 + lr;
    // frag-scatter constants for stsA
    const int s_mt  = lr >> 4;
    const int s_gid = lr & 7;
    const int s_hi  = (lr >> 3) & 1;
    const int s_ks  = lk >> 3;
    const int s_q   = (lk >> 2) & 1;
    const int s_w   = s_hi + 2 * s_q;
    const int s_off = (s_mt * 4 + s_ks) * 132 + (s_gid * 4) * 4 + s_w;
    // per-warp B stream base (advances 256 floats per kc within a gate slab)
    const float4* wbase = (const float4*)(g_Wf + (size_t)(jt * 4 + wn) * 4 * 48 * 256) + lane * 2;

    for (int t = 0; t < S_LEN; t++) {
        const float* x_t    = x + (size_t)t * BATCH * IN;
        const float* h_prev = t ? outs + (size_t)(t - 1) * BATCH * HID : h0;
        float*       h_out  = outs + (size_t)t * BATCH * HID;
        const float* Sp = (t & 1) ? g_stackB : g_stackA;
        float*       So = (t & 1) ? g_stackA : g_stackB;
        const float* dprev   = g_d   + ((t + 1) & 1) * (BATCH * SWID);
        const float* ctlprev = g_ctl + ((t + 1) & 1) * (BATCH * 3);
        float*       dcur    = g_d   + (t & 1) * (BATCH * SWID);
        float*       ctlcur  = g_ctl + (t & 1) * (BATCH * 3);

        float cpu = 0.f, cpo = 0.f, cnn = 1.f;
        if (t) {
            cpu = ctlprev[lb * 3 + 0];
            cpo = ctlprev[lb * 3 + 1];
            cnn = ctlprev[lb * 3 + 2];
        }
        const float* pX = x_t + (size_t)lb * IN + lk;
        const float* pS = Sp + (size_t)lb * (SDEP * SWID) + lk - IN;   // valid for kk in [IN,IS)
        const float* pD = dprev + (size_t)lb * SWID + lk - IN;
        const float* pH = h_prev + (size_t)lb * HID + lk - IS;

        auto ldgA = [&](int kc) -> float4 {
            const int kk = kc * 32 + lk;
            if (kk < IN) {
                return *(const float4*)(pX + kc * 32);
            } else if (kk < IS) {
                float4 s0 = *(const float4*)(pS + kc * 32);
                if (t == 0) return s0;
                float4 s1 = *(const float4*)(pS + SWID + kc * 32);
                float4 dv = *(const float4*)(pD + kc * 32);
                float4 v;
                v.x = cnn * s0.x + cpu * dv.x + cpo * s1.x;
                v.y = cnn * s0.y + cpu * dv.y + cpo * s1.y;
                v.z = cnn * s0.z + cpu * dv.z + cpo * s1.z;
                v.w = cnn * s0.w + cpu * dv.w + cpo * s1.w;
                return v;
            } else {
                return *(const float4*)(pH + kc * 32);
            }
        };
        auto stsA = [&](int buf, float4 v) {
            float* p = &sm[buf * BUFSZ + s_off];
            p[0]  = ftf32(v.x);
            p[4]  = ftf32(v.y);
            p[8]  = ftf32(v.z);
            p[12] = ftf32(v.w);
        };
        auto ldgB = [&](int kc, float4 bb[4][2]) {
#pragma unroll
            for (int g = 0; g < 4; g++) {
                const float4* p = wbase + (size_t)(g * 48 + kc) * 64;
                bb[g][0] = p[0];
                bb[g][1] = p[1];
            }
        };

        // ---- phase 1: gates GEMM, warp = 16m x (4 gates x 8j) ----
        float acc[4][4];
#pragma unroll
        for (int g = 0; g < 4; g++)
#pragma unroll
            for (int cc = 0; cc < 4; cc++) acc[g][cc] = 0.f;

        auto mma_step = [&](int buf, float4 (&bb)[4][2]) {
#pragma unroll
            for (int ks = 0; ks < 4; ks++) {
                const float4 af = *(const float4*)&sm[buf * BUFSZ + (wm * 4 + ks) * 132 + lane * 4];
                uint32_t a[4] = {__float_as_uint(af.x), __float_as_uint(af.y),
                                 __float_as_uint(af.z), __float_as_uint(af.w)};
#pragma unroll
                for (int g = 0; g < 4; g++) {
                    float2 s;
                    if (ks == 0)      s = make_float2(bb[g][0].x, bb[g][0].y);
                    else if (ks == 1) s = make_float2(bb[g][0].z, bb[g][0].w);
                    else if (ks == 2) s = make_float2(bb[g][1].x, bb[g][1].y);
                    else              s = make_float2(bb[g][1].z, bb[g][1].w);
                    uint32_t bf[2] = {__float_as_uint(s.x), __float_as_uint(s.y)};
                    mma_tf32(acc[g], a, bf);
                }
            }
        };

        float4 vA;
        float4 b0[4][2], b1[4][2];
        vA = ldgA(0);
        ldgB(0, b0);
        stsA(0, vA);
        vA = ldgA(1);
        ldgB(1, b1);
        for (int kc = 0; kc < 48; kc += 2) {
            // even half: compute kc (buf0/b0); vA holds A(kc+1)
            __syncthreads();
            stsA(1, vA);
            mma_step(0, b0);
            if (kc + 2 < 48) { vA = ldgA(kc + 2); ldgB(kc + 2, b0); }
            // odd half: compute kc+1 (buf1/b1); vA holds A(kc+2)
            __syncthreads();
            if (kc + 2 < 48) stsA(0, vA);
            mma_step(1, b1);
            if (kc + 3 < 48) { vA = ldgA(kc + 3); ldgB(kc + 3, b1); }
        }

        // ---- LSTM pointwise epilogue, direct from registers ----
        {
            const int jb = j0 + wn * 8 + (tig << 1);
            const float2 B0 = *(const float2*)(g_bias + jb);
            const float2 B1 = *(const float2*)(g_bias + HID + jb);
            const float2 B2 = *(const float2*)(g_bias + 2 * HID + jb);
            const float2 B3 = *(const float2*)(g_bias + 3 * HID + jb);
#pragma unroll
            for (int cc = 0; cc < 4; cc++) {
                const int row = wm * 16 + ((cc >> 1) << 3) + gi_r;
                const int b = bm0 + row;
                const int odd = cc & 1;
                const size_t off = (size_t)b * HID + jb + odd;
                float gi = acc[0][cc] + (odd ? B0.y : B0.x);
                float gf = acc[1][cc] + (odd ? B1.y : B1.x);
                float gg = acc[2][cc] + (odd ? B2.y : B2.x);
                float go = acc[3][cc] + (odd ? B3.y : B3.x);
                float iv = 1.f / (1.f + expf(-gi));
                float fv = 1.f / (1.f + expf(-gf));
                float gv = tanhf(gg);
                float ov = 1.f / (1.f + expf(-go));
                float cn_ = fv * g_c[off] + iv * gv;
                g_c[off]  = cn_;
                h_out[off] = ov * tanhf(cn_);
            }
        }

        // ---- barrier A (split): blend overlaps the wait ----
        unsigned myg;
        bar_arrive(&myg);
        blend_range(Sp, So, dprev, ctlprev, t == 0, bid, tid);
        bar_wait(myg);

        // ---- phase 2: d = tanh(h @ D_w^T + D_b); controls softmax ----
        if (bid < 64) {
            const int bx = bid & 7, by = bid >> 3;
            const int w0 = bx * 32, bm0d = by * 32;
            const int wm2 = warp >> 2, wn2 = warp & 3;
            const int arow = tid >> 3;          // valid for tid < 256
            const int kl2  = (tid & 7) << 2;
            float acc2[4] = {0.f, 0.f, 0.f, 0.f};
            for (int kc = 0; kc < HID; kc += 32) {
                if (tid < 256) {
                    const int kk = kc + kl2;
                    {
                        float4 v = *(const float4*)(h_out + (size_t)(bm0d + arow) * HID + kk);
                        float* p = &sm[arow * 36 + kl2];
                        p[0] = ftf32(v.x); p[1] = ftf32(v.y); p[2] = ftf32(v.z); p[3] = ftf32(v.w);
                    }
                    {
                        float4 v = *(const float4*)(D_w + (size_t)(w0 + arow) * HID + kk);
                        float* p = &sm[1152 + arow * 36 + kl2];
                        p[0] = ftf32(v.x); p[1] = ftf32(v.y); p[2] = ftf32(v.z); p[3] = ftf32(v.w);
                    }
                }
                __syncthreads();
                if (warp < 8) {
#pragma unroll
                    for (int ks = 0; ks < 4; ks++) {
                        const int k0 = ks * 8;
                        uint32_t a[4], bf[2];
                        const int m0 = wm2 * 16;
                        a[0] = __float_as_uint(sm[(m0 + gi_r) * 36 + k0 + tig]);
                        a[1] = __float_as_uint(sm[(m0 + 8 + gi_r) * 36 + k0 + tig]);
                        a[2] = __float_as_uint(sm[(m0 + gi_r) * 36 + k0 + tig + 4]);
                        a[3] = __float_as_uint(sm[(m0 + 8 + gi_r) * 36 + k0 + tig + 4]);
                        const int n0 = wn2 * 8;
                        bf[0] = __float_as_uint(sm[1152 + (n0 + gi_r) * 36 + k0 + tig]);
                        bf[1] = __float_as_uint(sm[1152 + (n0 + gi_r) * 36 + k0 + tig + 4]);
                        mma_tf32(acc2, a, bf);
                    }
                }
                __syncthreads();
            }
            if (warp < 8) {
#pragma unroll
                for (int cc = 0; cc < 4; cc++) {
                    const int row = wm2 * 16 + ((cc >> 1) << 3) + gi_r;
                    const int col = wn2 * 8 + (tig << 1) + (cc & 1);
                    dcur[(size_t)(bm0d + row) * SWID + w0 + col] =
                        tanhf(acc2[cc] + D_b[w0 + col]);
                }
            }
        } else if (bid < 72) {
            const int bm0c = (bid - 64) * 32;
            for (int q = 0; q < 2; q++) {
                const int b = bm0c + warp * 2 + q;
                float s0 = 0.f, s1 = 0.f, s2 = 0.f;
                for (int k = lane; k < HID; k += 32) {
                    float hv = h_out[(size_t)b * HID + k];
                    s0 += hv * A_w[k];
                    s1 += hv * A_w[HID + k];
                    s2 += hv * A_w[2 * HID + k];
                }
#pragma unroll
                for (int o = 16; o > 0; o >>= 1) {
                    s0 += __shfl_xor_sync(0xffffffffu, s0, o);
                    s1 += __shfl_xor_sync(0xffffffffu, s1, o);
                    s2 += __shfl_xor_sync(0xffffffffu, s2, o);
                }
                if (lane == 0) {
                    s0 += A_b[0]; s1 += A_b[1]; s2 += A_b[2];
                    float mx = fmaxf(s0, fmaxf(s1, s2));
                    float e0 = expf(s0 - mx), e1 = expf(s1 - mx), e2 = expf(s2 - mx);
                    float inv = 1.f / (e0 + e1 + e2);
                    ctlcur[b * 3 + 0] = e0 * inv;
                    ctlcur[b * 3 + 1] = e1 * inv;
                    ctlcur[b * 3 + 2] = e2 * inv;
                }
            }
        }
        gbar();   // d_t / ctl_t visible for step t+1
    }

    // ---- final stack: R_512 = blend(R_511, d_511, ctl_511) -> stackn ----
    blend_range(g_stackA, stackn, g_d + BATCH * SWID, g_ctl + BATCH * 3, 0, bid, tid);
}

// ---------------- launch ----------------
extern "C" void kernel_launch(void* const* d_in, const int* in_sizes, int n_in,
                              void* d_out, int out_size)
{
    const float* x    = (const float*)d_in[0];
    const float* h0   = (const float*)d_in[1];
    const float* c0   = (const float*)d_in[2];
    const float* st0  = (const float*)d_in[3];
    const float* W_ih = (const float*)d_in[4];
    const float* W_hh = (const float*)d_in[5];
    const float* b_ih = (const float*)d_in[6];
    const float* b_hh = (const float*)d_in[7];
    const float* A_w  = (const float*)d_in[8];
    const float* A_b  = (const float*)d_in[9];
    const float* D_w  = (const float*)d_in[10];
    const float* D_b  = (const float*)d_in[11];

    float* out    = (float*)d_out;
    float* outs   = out;
    float* hn     = outs + (size_t)S_LEN * BATCH * HID;
    float* cn     = hn + (size_t)BATCH * HID;
    float* stackn = cn + (size_t)BATCH * HID;

    float *sA, *cbuf;
    cudaGetSymbolAddress((void**)&sA, g_stackA);
    cudaGetSymbolAddress((void**)&cbuf, g_c);

    cudaMemcpyAsync(cbuf, c0, sizeof(float) * BATCH * HID, cudaMemcpyDeviceToDevice);
    cudaMemcpyAsync(sA, st0, sizeof(float) * BATCH * SDEP * SWID, cudaMemcpyDeviceToDevice);

    stackrnn_persistent<<<NB, NT>>>(x, h0, W_ih, W_hh, b_ih, b_hh,
                                    A_w, A_b, D_w, D_b, outs, stackn);

    cudaMemcpyAsync(hn, outs + (size_t)(S_LEN - 1) * BATCH * HID,
                    sizeof(float) * BATCH * HID, cudaMemcpyDeviceToDevice);
    cudaMemcpyAsync(cn, cbuf, sizeof(float) * BATCH * HID, cudaMemcpyDeviceToDevice);
}